// round 3
// baseline (speedup 1.0000x reference)
#include <cuda_runtime.h>
#include <math.h>
#include <stddef.h>

// Problem dims (fixed)
#define B_   64
#define T_   512
#define D_   1024
#define H_   1024
#define L_   4
#define G_   4096           // 4*H
#define O_   256
#define TB_  (T_ * B_)      // 32768

#define NBLK 128            // persistent-kernel grid (all co-resident: 1 block/SM, 148 SMs)
#define NTHR 256

// ---------------------------------------------------------------------------
// Device scratch (static globals — no allocation allowed)
// ---------------------------------------------------------------------------
__device__ float g_gates[(size_t)TB_ * G_];   // 512 MB: input-part of gates
__device__ float g_seq0[(size_t)TB_ * H_];    // 128 MB: layer output sequence ping
__device__ float g_seq1[(size_t)TB_ * H_];    // 128 MB: pong
__device__ float g_hA[B_ * H_];               // h ping
__device__ float g_hB[B_ * H_];               // h pong

__device__ unsigned g_bar_count = 0;
__device__ unsigned g_bar_gen   = 0;

// ---------------------------------------------------------------------------
// Packed f32x2 helpers (Blackwell FFMA2 path — full-rate fp32)
// ---------------------------------------------------------------------------
__device__ __forceinline__ unsigned long long ffma2(unsigned long long a,
                                                    unsigned long long b,
                                                    unsigned long long c) {
    unsigned long long d;
    asm("fma.rn.f32x2 %0, %1, %2, %3;" : "=l"(d) : "l"(a), "l"(b), "l"(c));
    return d;
}
__device__ __forceinline__ unsigned long long pack2(float x, float y) {
    unsigned long long r;
    asm("mov.b64 %0, {%1, %2};" : "=l"(r) : "f"(x), "f"(y));
    return r;
}
__device__ __forceinline__ float2 unpack2(unsigned long long v) {
    float2 r;
    asm("mov.b64 {%0, %1}, %2;" : "=f"(r.x), "=f"(r.y) : "l"(v));
    return r;
}

// ---------------------------------------------------------------------------
// Software grid barrier (all NBLK blocks resident => no deadlock).
// Writers: __threadfence before arrive makes prior STGs L2-visible.
// Readers: re-read shared data with __ldcg (L2) after the barrier.
// ---------------------------------------------------------------------------
__device__ __forceinline__ void grid_barrier() {
    __threadfence();
    __syncthreads();
    if (threadIdx.x == 0) {
        unsigned gen = *(volatile unsigned*)&g_bar_gen;
        unsigned old = atomicAdd(&g_bar_count, 1u);
        if (old == NBLK - 1) {
            g_bar_count = 0;          // safe: everyone else is spinning on gen
            __threadfence();
            atomicAdd(&g_bar_gen, 1u);
        } else {
            while (*(volatile unsigned*)&g_bar_gen == gen) { }
        }
        __threadfence();
    }
    __syncthreads();
}

// ---------------------------------------------------------------------------
// Input GEMM: gates[m, j] = bih[j] + bhh[j] + sum_k A[m,k] * Wih[j,k]
// M = 32768 (m = t*B + b), N = 4096, K = 1024.
// BM=BN=128, BK=16, 256 threads, 8x8 per thread (f32x2-packed along M).
// ---------------------------------------------------------------------------
#define BM 128
#define BN 128
#define BK 16

template <bool LAYER0>
__global__ void __launch_bounds__(256)
gemm_gates(const float* __restrict__ x,
           const float* __restrict__ Wih_all,
           const float* __restrict__ bih_all,
           const float* __restrict__ bhh_all,
           int layer, int in_sel)
{
    __shared__ float As[BK][BM + 4];   // k-major (transposed), padded
    __shared__ float Ws[BK][BN + 4];

    const float* A;
    if (LAYER0) A = x;
    else        A = (in_sel == 0) ? g_seq0 : g_seq1;

    const float* W  = Wih_all + (size_t)layer * G_ * H_;
    const float* bi = bih_all + (size_t)layer * G_;
    const float* bh = bhh_all + (size_t)layer * G_;

    const int m0  = blockIdx.y * BM;
    const int n0  = blockIdx.x * BN;
    const int tid = threadIdx.x;
    const int tm  = tid >> 4;
    const int tn  = tid & 15;

    unsigned long long acc[4][8];
#pragma unroll
    for (int i = 0; i < 4; i++)
#pragma unroll
        for (int j = 0; j < 8; j++) acc[i][j] = 0ull;

    for (int k0 = 0; k0 < H_; k0 += BK) {
#pragma unroll
        for (int i = 0; i < 2; i++) {
            int idx = tid + i * 256;
            int row = idx >> 2;
            int kq  = (idx & 3) << 2;
            int gr  = m0 + row;
            const float* ap;
            if (LAYER0) {
                int t = gr >> 6;          // m = t*B + b, B = 64
                int b = gr & 63;
                ap = A + ((size_t)b * T_ + t) * D_ + k0 + kq;
            } else {
                ap = A + (size_t)gr * H_ + k0 + kq;
            }
            float4 v = *reinterpret_cast<const float4*>(ap);
            As[kq + 0][row] = v.x;
            As[kq + 1][row] = v.y;
            As[kq + 2][row] = v.z;
            As[kq + 3][row] = v.w;
        }
#pragma unroll
        for (int i = 0; i < 2; i++) {
            int idx = tid + i * 256;
            int row = idx >> 2;
            int kq  = (idx & 3) << 2;
            const float* wp = W + (size_t)(n0 + row) * H_ + k0 + kq;
            float4 v = *reinterpret_cast<const float4*>(wp);
            Ws[kq + 0][row] = v.x;
            Ws[kq + 1][row] = v.y;
            Ws[kq + 2][row] = v.z;
            Ws[kq + 3][row] = v.w;
        }
        __syncthreads();

#pragma unroll
        for (int kk = 0; kk < BK; kk++) {
            ulonglong2 a01 = *reinterpret_cast<const ulonglong2*>(&As[kk][tm * 8]);
            ulonglong2 a23 = *reinterpret_cast<const ulonglong2*>(&As[kk][tm * 8 + 4]);
            unsigned long long a2[4] = { a01.x, a01.y, a23.x, a23.y };
            float4 b0 = *reinterpret_cast<const float4*>(&Ws[kk][tn * 8]);
            float4 b1 = *reinterpret_cast<const float4*>(&Ws[kk][tn * 8 + 4]);
            float bb[8] = { b0.x, b0.y, b0.z, b0.w, b1.x, b1.y, b1.z, b1.w };
#pragma unroll
            for (int j = 0; j < 8; j++) {
                unsigned long long bj = pack2(bb[j], bb[j]);
#pragma unroll
                for (int i = 0; i < 4; i++)
                    acc[i][j] = ffma2(a2[i], bj, acc[i][j]);
            }
        }
        __syncthreads();
    }

#pragma unroll
    for (int j = 0; j < 8; j++) {
        int col = n0 + tn * 8 + j;
        float bias = bi[col] + bh[col];
#pragma unroll
        for (int i = 0; i < 4; i++) {
            int r = m0 + tm * 8 + 2 * i;
            float2 v = unpack2(acc[i][j]);
            g_gates[(size_t)r * G_ + col]       = v.x + bias;
            g_gates[(size_t)(r + 1) * G_ + col] = v.y + bias;
        }
    }
}

// ---------------------------------------------------------------------------
// Persistent recurrent kernel: one launch per layer, 512 timesteps inside,
// grid barrier between steps. Whh slice (32 gate-rows x 1024) lives in SMEM
// for the whole layer. Cell state c lives in registers.
//
// Block jb owns h-columns [jb*8, jb*8+8) => gate rows {g*1024 + jb*8+jj}.
// 256 threads: c = tid&31 (gate col 0..31), bg = tid>>5 (8 b-rows each).
// SMEM: Ws [k/4][32][4] interleaved (131072 B) + Hs [32][68] (8704 B)
//       + pre [64][34] (8704 B) = 148480 B.
// ---------------------------------------------------------------------------
#define BK2 32
#define WS_FLOATS   (32 * 1024)
#define HS_FLOATS   (BK2 * 68)
#define PRE_FLOATS  (64 * 34)
#define PSMEM_BYTES ((WS_FLOATS + HS_FLOATS + PRE_FLOATS) * 4)

__global__ void __launch_bounds__(NTHR, 1)
lstm_persist(const float* __restrict__ Whh_all, int layer, int out_sel)
{
    extern __shared__ float smem[];
    float* Ws  = smem;                          // interleaved: (k>>2)*128 + c*4 + (k&3)
    float* Hs  = smem + WS_FLOATS;              // Hs[k][row], row-pitch 68
    float* pre = smem + WS_FLOATS + HS_FLOATS;  // pre[b][c],  row-pitch 34

    const float* W      = Whh_all + (size_t)layer * G_ * H_;
    float*       seqout = (out_sel == 0) ? g_seq0 : g_seq1;

    const int jb  = blockIdx.x;
    const int tid = threadIdx.x;
    const int c   = tid & 31;        // block-local gate col
    const int bg  = tid >> 5;        // 0..7, rows [bg*8, bg*8+8)

    // Elementwise-phase identity (fixed for whole layer): 2 cells per thread
    const int eb  = tid >> 2;        // batch row 0..63
    const int ejj = (tid & 3) * 2;   // jj0 (even)
    const int jg0 = jb * 8 + ejj;    // global h column of first cell

    // ---- load Whh slice into SMEM (one-time) ----
    {
        int cc   = tid & 31;
        int wrow = (cc >> 3) * H_ + jb * 8 + (cc & 7);
        const float* wp = W + (size_t)wrow * H_;
#pragma unroll 4
        for (int j = 0; j < 32; j++) {
            int kk = (tid >> 5) * 4 + j * 32;
            float4 v = *reinterpret_cast<const float4*>(wp + kk);
            *reinterpret_cast<float4*>(&Ws[(kk >> 2) * 128 + cc * 4]) = v;
        }
    }

    // ---- zero initial h (g_hA) ----
    g_hA[jb * 512 + tid]       = 0.0f;
    g_hA[jb * 512 + 256 + tid] = 0.0f;

    float2 creg = make_float2(0.0f, 0.0f);   // cell state (registers)

    grid_barrier();   // W in SMEM + h zeroed, visible everywhere

    for (int t = 0; t < T_; t++) {
        const float* hin  = (t & 1) ? g_hB : g_hA;
        float*       hout = (t & 1) ? g_hA : g_hB;

        // Prefetch this step's input-gate contributions (DRAM latency hidden
        // behind the whole k-loop).
        const float* grow = g_gates + ((size_t)(t * B_ + eb)) * G_ + jg0;
        float2 G0 = *reinterpret_cast<const float2*>(grow);
        float2 G1 = *reinterpret_cast<const float2*>(grow + H_);
        float2 G2 = *reinterpret_cast<const float2*>(grow + 2 * H_);
        float2 G3 = *reinterpret_cast<const float2*>(grow + 3 * H_);

        unsigned long long acc0 = 0ull, acc1 = 0ull, acc2 = 0ull, acc3 = 0ull;

        // chunk-0 h prefetch (L2-coherent loads: h changes every step)
        const int r0 = tid >> 3,          kq0 = (tid & 7) * 4;         // idx = tid
        const int r1 = (tid + 256) >> 3,  kq1 = ((tid + 256) & 7) * 4; // idx = tid+256
        float4 h0 = __ldcg(reinterpret_cast<const float4*>(hin + r0 * H_ + kq0));
        float4 h1 = __ldcg(reinterpret_cast<const float4*>(hin + r1 * H_ + kq1));

        for (int ch = 0; ch < H_ / BK2; ch++) {
            __syncthreads();   // prior chunk's compute done before overwrite
            Hs[(kq0 + 0) * 68 + r0] = h0.x;
            Hs[(kq0 + 1) * 68 + r0] = h0.y;
            Hs[(kq0 + 2) * 68 + r0] = h0.z;
            Hs[(kq0 + 3) * 68 + r0] = h0.w;
            Hs[(kq1 + 0) * 68 + r1] = h1.x;
            Hs[(kq1 + 1) * 68 + r1] = h1.y;
            Hs[(kq1 + 2) * 68 + r1] = h1.z;
            Hs[(kq1 + 3) * 68 + r1] = h1.w;
            __syncthreads();

            if (ch + 1 < H_ / BK2) {
                int kb = (ch + 1) * BK2;
                h0 = __ldcg(reinterpret_cast<const float4*>(hin + r0 * H_ + kb + kq0));
                h1 = __ldcg(reinterpret_cast<const float4*>(hin + r1 * H_ + kb + kq1));
            }

            const int kbase = ch * BK2;
#pragma unroll
            for (int kk = 0; kk < BK2; kk += 4) {
                float4 w4 = *reinterpret_cast<const float4*>(
                    &Ws[((kbase + kk) >> 2) * 128 + c * 4]);
                float wv[4] = { w4.x, w4.y, w4.z, w4.w };
#pragma unroll
                for (int u = 0; u < 4; u++) {
                    const float* hp = &Hs[(kk + u) * 68 + bg * 8];
                    ulonglong2 a01 = *reinterpret_cast<const ulonglong2*>(hp);
                    ulonglong2 a23 = *reinterpret_cast<const ulonglong2*>(hp + 4);
                    unsigned long long wq = pack2(wv[u], wv[u]);
                    acc0 = ffma2(a01.x, wq, acc0);
                    acc1 = ffma2(a01.y, wq, acc1);
                    acc2 = ffma2(a23.x, wq, acc2);
                    acc3 = ffma2(a23.y, wq, acc3);
                }
            }
        }

        // Stage recurrent pre-activations
        __syncthreads();
        {
            float2 v;
            v = unpack2(acc0); pre[(bg * 8 + 0) * 34 + c] = v.x; pre[(bg * 8 + 1) * 34 + c] = v.y;
            v = unpack2(acc1); pre[(bg * 8 + 2) * 34 + c] = v.x; pre[(bg * 8 + 3) * 34 + c] = v.y;
            v = unpack2(acc2); pre[(bg * 8 + 4) * 34 + c] = v.x; pre[(bg * 8 + 5) * 34 + c] = v.y;
            v = unpack2(acc3); pre[(bg * 8 + 6) * 34 + c] = v.x; pre[(bg * 8 + 7) * 34 + c] = v.y;
        }
        __syncthreads();

        // Elementwise: 2 cells per thread (b = eb, jj = ejj, ejj+1)
        {
            const float* pr = &pre[eb * 34];
            float i0 = pr[ejj]          + G0.x, i1 = pr[ejj + 1]      + G0.y;
            float f0 = pr[8 + ejj]      + G1.x, f1 = pr[8 + ejj + 1]  + G1.y;
            float g0 = pr[16 + ejj]     + G2.x, g1 = pr[16 + ejj + 1] + G2.y;
            float o0 = pr[24 + ejj]     + G3.x, o1 = pr[24 + ejj + 1] + G3.y;
            i0 = 1.0f / (1.0f + __expf(-i0));
            i1 = 1.0f / (1.0f + __expf(-i1));
            f0 = 1.0f / (1.0f + __expf(-f0));
            f1 = 1.0f / (1.0f + __expf(-f1));
            o0 = 1.0f / (1.0f + __expf(-o0));
            o1 = 1.0f / (1.0f + __expf(-o1));
            g0 = tanhf(g0);
            g1 = tanhf(g1);
            creg.x = f0 * creg.x + i0 * g0;
            creg.y = f1 * creg.y + i1 * g1;
            float2 hv = make_float2(o0 * tanhf(creg.x), o1 * tanhf(creg.y));
            *reinterpret_cast<float2*>(&hout[eb * H_ + jg0]) = hv;
            *reinterpret_cast<float2*>(&seqout[(size_t)(t * B_ + eb) * H_ + jg0]) = hv;
        }

        grid_barrier();
    }
}

// ---------------------------------------------------------------------------
// Final FC: out[b, o] = fc_b[o] + dot(h_final[b, :], fc_w[o, :])
// T=512 even => final h is in g_hA.
// ---------------------------------------------------------------------------
__global__ void __launch_bounds__(256)
fc_kernel(const float* __restrict__ fc_w, const float* __restrict__ fc_b,
          float* __restrict__ out)
{
    int b = blockIdx.x;
    int o = threadIdx.x;
    const float4* hv = reinterpret_cast<const float4*>(&g_hA[b * H_]);
    const float4* wv = reinterpret_cast<const float4*>(&fc_w[(size_t)o * H_]);
    float s = 0.0f;
#pragma unroll 8
    for (int k = 0; k < H_ / 4; k++) {
        float4 a = hv[k];
        float4 w = wv[k];
        s += a.x * w.x + a.y * w.y + a.z * w.z + a.w * w.w;
    }
    out[b * O_ + o] = s + fc_b[o];
}

// ---------------------------------------------------------------------------
// Launch: 9 graph nodes total (4 GEMM + 4 persistent + 1 FC)
// ---------------------------------------------------------------------------
extern "C" void kernel_launch(void* const* d_in, const int* in_sizes, int n_in,
                              void* d_out, int out_size)
{
    (void)in_sizes; (void)n_in; (void)out_size;
    const float* x    = (const float*)d_in[0];
    const float* Wih  = (const float*)d_in[1];
    const float* Whh  = (const float*)d_in[2];
    const float* bih  = (const float*)d_in[3];
    const float* bhh  = (const float*)d_in[4];
    const float* fc_w = (const float*)d_in[5];
    const float* fc_b = (const float*)d_in[6];
    float* out = (float*)d_out;

    cudaFuncSetAttribute(lstm_persist,
                         cudaFuncAttributeMaxDynamicSharedMemorySize, PSMEM_BYTES);

    const dim3 ggrid(G_ / BN, TB_ / BM);   // (32, 256)
    // routing: l0: x->seq0, l1: seq0->seq1, l2: seq1->seq0, l3: seq0->seq1
    const int in_sel[L_]  = { 0, 0, 1, 0 };
    const int out_sel[L_] = { 0, 1, 0, 1 };

    for (int l = 0; l < L_; l++) {
        if (l == 0)
            gemm_gates<true ><<<ggrid, 256>>>(x, Wih, bih, bhh, l, 0);
        else
            gemm_gates<false><<<ggrid, 256>>>(nullptr, Wih, bih, bhh, l, in_sel[l]);
        lstm_persist<<<NBLK, NTHR, PSMEM_BYTES>>>(Whh, l, out_sel[l]);
    }
    fc_kernel<<<B_, 256>>>(fc_w, fc_b, out);
}

// round 5
// speedup vs baseline: 1.1156x; 1.1156x over previous
#include <cuda_runtime.h>
#include <math.h>
#include <stddef.h>
#include <stdint.h>
#include <mma.h>

using namespace nvcuda;

// Problem dims (fixed)
#define B_   64
#define T_   512
#define D_   1024
#define H_   1024
#define L_   4
#define G_   4096           // 4*H
#define O_   256
#define TB_  (T_ * B_)      // 32768

#define NBLK 128            // persistent-kernel grid
#define NTHR 256

// ---------------------------------------------------------------------------
// Device scratch (static globals — no allocation allowed)
// ---------------------------------------------------------------------------
__device__ float g_gates[(size_t)TB_ * G_];   // 512 MB: input-part of gates
__device__ float g_seq0[(size_t)TB_ * H_];    // 128 MB
__device__ float g_seq1[(size_t)TB_ * H_];    // 128 MB
__device__ float g_hA[B_ * H_];
__device__ float g_hB[B_ * H_];

__device__ unsigned g_bar_count = 0;
__device__ unsigned g_bar_gen   = 0;

// ---------------------------------------------------------------------------
// Packed f32x2 helpers
// ---------------------------------------------------------------------------
__device__ __forceinline__ unsigned long long ffma2(unsigned long long a,
                                                    unsigned long long b,
                                                    unsigned long long c) {
    unsigned long long d;
    asm("fma.rn.f32x2 %0, %1, %2, %3;" : "=l"(d) : "l"(a), "l"(b), "l"(c));
    return d;
}
__device__ __forceinline__ unsigned long long pack2(float x, float y) {
    unsigned long long r;
    asm("mov.b64 %0, {%1, %2};" : "=l"(r) : "f"(x), "f"(y));
    return r;
}
__device__ __forceinline__ float2 unpack2(unsigned long long v) {
    float2 r;
    asm("mov.b64 {%0, %1}, %2;" : "=f"(r.x), "=f"(r.y) : "l"(v));
    return r;
}

// ---------------------------------------------------------------------------
// Software grid barrier (all NBLK blocks resident)
// ---------------------------------------------------------------------------
__device__ __forceinline__ void grid_barrier() {
    __threadfence();
    __syncthreads();
    if (threadIdx.x == 0) {
        unsigned gen = *(volatile unsigned*)&g_bar_gen;
        unsigned old = atomicAdd(&g_bar_count, 1u);
        if (old == NBLK - 1) {
            g_bar_count = 0;
            __threadfence();
            atomicAdd(&g_bar_gen, 1u);
        } else {
            while (*(volatile unsigned*)&g_bar_gen == gen) { }
        }
        __threadfence();
    }
    __syncthreads();
}

// ---------------------------------------------------------------------------
// cp.async helpers (sm_80-baseline PTX — safe for plain sm_103 target)
// ---------------------------------------------------------------------------
__device__ __forceinline__ uint32_t smem_u32(const void* p) {
    uint32_t a;
    asm("{ .reg .u64 t; cvta.to.shared.u64 t, %1; cvt.u32.u64 %0, t; }"
        : "=r"(a) : "l"(p));
    return a;
}
__device__ __forceinline__ void cp16(uint32_t dst, const void* src) {
    asm volatile("cp.async.cg.shared.global [%0], [%1], 16;"
                 :: "r"(dst), "l"(src));
}
__device__ __forceinline__ void cp_commit() {
    asm volatile("cp.async.commit_group;" ::: "memory");
}
template <int N>
__device__ __forceinline__ void cp_wait() {
    asm volatile("cp.async.wait_group %0;" :: "n"(N) : "memory");
}

// ===========================================================================
// WMMA tf32 input GEMM:
//   gates[m, n] = bias[n] + sum_k A[m,k] * W[n,k]      (C = A · Wᵀ)
//   M = 32768, N = 4096, K = 1024.
// Tile: BM=128 x BN=128, BK=16, 256 threads (8 warps, each 32x64 via 2x4
// 16x16x8 tf32 fragments). cp.async 2-stage double buffer.
// ===========================================================================
#define BM 128
#define BN 128
#define BK 16
#define APITCH 20                       // floats; 80 B rows (16B-aligned)
#define STG_FLOATS (BM * APITCH)        // 2560 floats per (A|W) stage
#define CPITCH 68

// static smem: 2 A stages + 2 W stages + 128 bias = 10368 floats = 41472 B
#define GEMM_SM_FLOATS (4 * STG_FLOATS + 128)

template <bool LAYER0>
__device__ __forceinline__ void load_stage(float* As, float* Ws, int s, int c,
                                           const float* __restrict__ A,
                                           const float* __restrict__ W,
                                           int m0, int n0, int tid)
{
    const int k0 = c * BK;
    float* as = As + s * STG_FLOATS;
    float* ws = Ws + s * STG_FLOATS;
#pragma unroll
    for (int i = 0; i < 2; i++) {             // A: 128 rows x 4 segs of 16B
        int idx = tid + i * 256;
        int row = idx >> 2, seg = idx & 3;
        const float* src;
        if (LAYER0) {
            int m = m0 + row;                 // m = t*64 + b ; x is [B,T,D]
            src = A + ((size_t)(m & 63) * T_ + (m >> 6)) * D_ + k0 + seg * 4;
        } else {
            src = A + (size_t)(m0 + row) * H_ + k0 + seg * 4;
        }
        cp16(smem_u32(&as[row * APITCH + seg * 4]), src);
    }
#pragma unroll
    for (int i = 0; i < 2; i++) {             // W: 128 rows x 4 segs
        int idx = tid + i * 256;
        int row = idx >> 2, seg = idx & 3;
        cp16(smem_u32(&ws[row * APITCH + seg * 4]),
             W + (size_t)(n0 + row) * H_ + k0 + seg * 4);
    }
    cp_commit();
}

template <bool LAYER0>
__global__ void __launch_bounds__(256)
gemm_gates_tc(const float* __restrict__ x,
              const float* __restrict__ Wih_all,
              const float* __restrict__ bih_all,
              const float* __restrict__ bhh_all,
              int layer, int in_sel)
{
    __shared__ float sm[GEMM_SM_FLOATS];
    float* As    = sm;
    float* Ws    = sm + 2 * STG_FLOATS;
    float* biasS = sm + 4 * STG_FLOATS;
    float* Cbuf  = sm;                        // epilogue overlay [128][68]

    const float* A = LAYER0 ? x : (in_sel == 0 ? g_seq0 : g_seq1);
    const float* W = Wih_all + (size_t)layer * G_ * H_;

    const int tid = threadIdx.x;
    const int n0  = blockIdx.x * BN;
    const int m0  = blockIdx.y * BM;
    const int wid = tid >> 5;
    const int wm  = wid & 3;                  // m-tile 0..3 (32 rows each)
    const int wn  = wid >> 2;                 // n-half 0..1 (64 cols each)

    if (tid < 128)
        biasS[tid] = bih_all[(size_t)layer * G_ + n0 + tid]
                   + bhh_all[(size_t)layer * G_ + n0 + tid];

    wmma::fragment<wmma::accumulator, 16, 16, 8, float> cf[2][4];
#pragma unroll
    for (int i = 0; i < 2; i++)
#pragma unroll
        for (int j = 0; j < 4; j++) wmma::fill_fragment(cf[i][j], 0.0f);

    load_stage<LAYER0>(As, Ws, 0, 0, A, W, m0, n0, tid);

    const int NC = H_ / BK;                   // 64
    for (int c = 0; c < NC; c++) {
        const int s = c & 1;
        if (c + 1 < NC) {
            load_stage<LAYER0>(As, Ws, s ^ 1, c + 1, A, W, m0, n0, tid);
            cp_wait<1>();
        } else {
            cp_wait<0>();
        }
        __syncthreads();

        const float* as = As + s * STG_FLOATS;
        const float* ws = Ws + s * STG_FLOATS;
#pragma unroll
        for (int kk = 0; kk < BK; kk += 8) {
            wmma::fragment<wmma::matrix_a, 16, 16, 8, wmma::precision::tf32,
                           wmma::row_major> af[2];
            wmma::fragment<wmma::matrix_b, 16, 16, 8, wmma::precision::tf32,
                           wmma::col_major> bf[4];
#pragma unroll
            for (int i = 0; i < 2; i++) {
                wmma::load_matrix_sync(af[i],
                    as + (wm * 32 + i * 16) * APITCH + kk, APITCH);
#pragma unroll
                for (int e = 0; e < af[i].num_elements; e++)
                    af[i].x[e] = wmma::__float_to_tf32(af[i].x[e]);
            }
#pragma unroll
            for (int j = 0; j < 4; j++) {
                wmma::load_matrix_sync(bf[j],
                    ws + (wn * 64 + j * 16) * APITCH + kk, APITCH);
#pragma unroll
                for (int e = 0; e < bf[j].num_elements; e++)
                    bf[j].x[e] = wmma::__float_to_tf32(bf[j].x[e]);
            }
#pragma unroll
            for (int i = 0; i < 2; i++)
#pragma unroll
                for (int j = 0; j < 4; j++)
                    wmma::mma_sync(cf[i][j], af[i], bf[j], cf[i][j]);
        }
        __syncthreads();
    }

    // Epilogue: two halves (n-cols 0..63, 64..127) staged through SMEM,
    // bias fused, float4 stores to g_gates.
#pragma unroll
    for (int half = 0; half < 2; half++) {
        if (wn == half) {
#pragma unroll
            for (int i = 0; i < 2; i++)
#pragma unroll
                for (int j = 0; j < 4; j++)
                    wmma::store_matrix_sync(
                        &Cbuf[(wm * 32 + i * 16) * CPITCH + j * 16],
                        cf[i][j], CPITCH, wmma::mem_row_major);
        }
        __syncthreads();
#pragma unroll
        for (int q = 0; q < 8; q++) {
            int lin = q * 256 + tid;          // 0..2047 float4s
            int row = lin >> 4;               // 128 rows x 16 f4
            int c4  = lin & 15;
            float4 v = *reinterpret_cast<const float4*>(&Cbuf[row * CPITCH + c4 * 4]);
            int n = half * 64 + c4 * 4;
            v.x += biasS[n + 0];
            v.y += biasS[n + 1];
            v.z += biasS[n + 2];
            v.w += biasS[n + 3];
            *reinterpret_cast<float4*>(
                &g_gates[(size_t)(m0 + row) * G_ + n0 + n]) = v;
        }
        __syncthreads();
    }
}

// ---------------------------------------------------------------------------
// Persistent recurrent kernel (unchanged from R3): one launch per layer,
// Whh slice in SMEM, c in registers, grid barrier between steps.
// ---------------------------------------------------------------------------
#define BK2 32
#define WS_FLOATS   (32 * 1024)
#define HS_FLOATS   (BK2 * 68)
#define PRE_FLOATS  (64 * 34)
#define PSMEM_BYTES ((WS_FLOATS + HS_FLOATS + PRE_FLOATS) * 4)

__global__ void __launch_bounds__(NTHR, 1)
lstm_persist(const float* __restrict__ Whh_all, int layer, int out_sel)
{
    extern __shared__ float smemf[];
    float* Ws  = smemf;
    float* Hs  = smemf + WS_FLOATS;
    float* pre = smemf + WS_FLOATS + HS_FLOATS;

    const float* W      = Whh_all + (size_t)layer * G_ * H_;
    float*       seqout = (out_sel == 0) ? g_seq0 : g_seq1;

    const int jb  = blockIdx.x;
    const int tid = threadIdx.x;
    const int c   = tid & 31;
    const int bg  = tid >> 5;

    const int eb  = tid >> 2;
    const int ejj = (tid & 3) * 2;
    const int jg0 = jb * 8 + ejj;

    {
        int cc   = tid & 31;
        int wrow = (cc >> 3) * H_ + jb * 8 + (cc & 7);
        const float* wp = W + (size_t)wrow * H_;
#pragma unroll 4
        for (int j = 0; j < 32; j++) {
            int kk = (tid >> 5) * 4 + j * 32;
            float4 v = *reinterpret_cast<const float4*>(wp + kk);
            *reinterpret_cast<float4*>(&Ws[(kk >> 2) * 128 + cc * 4]) = v;
        }
    }

    g_hA[jb * 512 + tid]       = 0.0f;
    g_hA[jb * 512 + 256 + tid] = 0.0f;

    float2 creg = make_float2(0.0f, 0.0f);

    grid_barrier();

    for (int t = 0; t < T_; t++) {
        const float* hin  = (t & 1) ? g_hB : g_hA;
        float*       hout = (t & 1) ? g_hA : g_hB;

        const float* grow = g_gates + ((size_t)(t * B_ + eb)) * G_ + jg0;
        float2 G0 = *reinterpret_cast<const float2*>(grow);
        float2 G1 = *reinterpret_cast<const float2*>(grow + H_);
        float2 G2 = *reinterpret_cast<const float2*>(grow + 2 * H_);
        float2 G3 = *reinterpret_cast<const float2*>(grow + 3 * H_);

        unsigned long long acc0 = 0ull, acc1 = 0ull, acc2 = 0ull, acc3 = 0ull;

        const int r0 = tid >> 3,          kq0 = (tid & 7) * 4;
        const int r1 = (tid + 256) >> 3,  kq1 = ((tid + 256) & 7) * 4;
        float4 h0 = __ldcg(reinterpret_cast<const float4*>(hin + r0 * H_ + kq0));
        float4 h1 = __ldcg(reinterpret_cast<const float4*>(hin + r1 * H_ + kq1));

        for (int ch = 0; ch < H_ / BK2; ch++) {
            __syncthreads();
            Hs[(kq0 + 0) * 68 + r0] = h0.x;
            Hs[(kq0 + 1) * 68 + r0] = h0.y;
            Hs[(kq0 + 2) * 68 + r0] = h0.z;
            Hs[(kq0 + 3) * 68 + r0] = h0.w;
            Hs[(kq1 + 0) * 68 + r1] = h1.x;
            Hs[(kq1 + 1) * 68 + r1] = h1.y;
            Hs[(kq1 + 2) * 68 + r1] = h1.z;
            Hs[(kq1 + 3) * 68 + r1] = h1.w;
            __syncthreads();

            if (ch + 1 < H_ / BK2) {
                int kb = (ch + 1) * BK2;
                h0 = __ldcg(reinterpret_cast<const float4*>(hin + r0 * H_ + kb + kq0));
                h1 = __ldcg(reinterpret_cast<const float4*>(hin + r1 * H_ + kb + kq1));
            }

            const int kbase = ch * BK2;
#pragma unroll
            for (int kk = 0; kk < BK2; kk += 4) {
                float4 w4 = *reinterpret_cast<const float4*>(
                    &Ws[((kbase + kk) >> 2) * 128 + c * 4]);
                float wv[4] = { w4.x, w4.y, w4.z, w4.w };
#pragma unroll
                for (int u = 0; u < 4; u++) {
                    const float* hp = &Hs[(kk + u) * 68 + bg * 8];
                    ulonglong2 a01 = *reinterpret_cast<const ulonglong2*>(hp);
                    ulonglong2 a23 = *reinterpret_cast<const ulonglong2*>(hp + 4);
                    unsigned long long wq = pack2(wv[u], wv[u]);
                    acc0 = ffma2(a01.x, wq, acc0);
                    acc1 = ffma2(a01.y, wq, acc1);
                    acc2 = ffma2(a23.x, wq, acc2);
                    acc3 = ffma2(a23.y, wq, acc3);
                }
            }
        }

        __syncthreads();
        {
            float2 v;
            v = unpack2(acc0); pre[(bg * 8 + 0) * 34 + c] = v.x; pre[(bg * 8 + 1) * 34 + c] = v.y;
            v = unpack2(acc1); pre[(bg * 8 + 2) * 34 + c] = v.x; pre[(bg * 8 + 3) * 34 + c] = v.y;
            v = unpack2(acc2); pre[(bg * 8 + 4) * 34 + c] = v.x; pre[(bg * 8 + 5) * 34 + c] = v.y;
            v = unpack2(acc3); pre[(bg * 8 + 6) * 34 + c] = v.x; pre[(bg * 8 + 7) * 34 + c] = v.y;
        }
        __syncthreads();

        {
            const float* pr = &pre[eb * 34];
            float i0 = pr[ejj]      + G0.x, i1 = pr[ejj + 1]      + G0.y;
            float f0 = pr[8 + ejj]  + G1.x, f1 = pr[8 + ejj + 1]  + G1.y;
            float g0 = pr[16 + ejj] + G2.x, g1 = pr[16 + ejj + 1] + G2.y;
            float o0 = pr[24 + ejj] + G3.x, o1 = pr[24 + ejj + 1] + G3.y;
            i0 = 1.0f / (1.0f + __expf(-i0));
            i1 = 1.0f / (1.0f + __expf(-i1));
            f0 = 1.0f / (1.0f + __expf(-f0));
            f1 = 1.0f / (1.0f + __expf(-f1));
            o0 = 1.0f / (1.0f + __expf(-o0));
            o1 = 1.0f / (1.0f + __expf(-o1));
            g0 = tanhf(g0);
            g1 = tanhf(g1);
            creg.x = f0 * creg.x + i0 * g0;
            creg.y = f1 * creg.y + i1 * g1;
            float2 hv = make_float2(o0 * tanhf(creg.x), o1 * tanhf(creg.y));
            *reinterpret_cast<float2*>(&hout[eb * H_ + jg0]) = hv;
            *reinterpret_cast<float2*>(&seqout[(size_t)(t * B_ + eb) * H_ + jg0]) = hv;
        }

        grid_barrier();
    }
}

// ---------------------------------------------------------------------------
// Final FC
// ---------------------------------------------------------------------------
__global__ void __launch_bounds__(256)
fc_kernel(const float* __restrict__ fc_w, const float* __restrict__ fc_b,
          float* __restrict__ out)
{
    int b = blockIdx.x;
    int o = threadIdx.x;
    const float4* hv = reinterpret_cast<const float4*>(&g_hA[b * H_]);
    const float4* wv = reinterpret_cast<const float4*>(&fc_w[(size_t)o * H_]);
    float s = 0.0f;
#pragma unroll 8
    for (int k = 0; k < H_ / 4; k++) {
        float4 a = hv[k];
        float4 w = wv[k];
        s += a.x * w.x + a.y * w.y + a.z * w.z + a.w * w.w;
    }
    out[b * O_ + o] = s + fc_b[o];
}

// ---------------------------------------------------------------------------
// Launch: 9 graph nodes (4 wmma-GEMM + 4 persistent + 1 FC)
// ---------------------------------------------------------------------------
extern "C" void kernel_launch(void* const* d_in, const int* in_sizes, int n_in,
                              void* d_out, int out_size)
{
    (void)in_sizes; (void)n_in; (void)out_size;
    const float* x    = (const float*)d_in[0];
    const float* Wih  = (const float*)d_in[1];
    const float* Whh  = (const float*)d_in[2];
    const float* bih  = (const float*)d_in[3];
    const float* bhh  = (const float*)d_in[4];
    const float* fc_w = (const float*)d_in[5];
    const float* fc_b = (const float*)d_in[6];
    float* out = (float*)d_out;

    cudaFuncSetAttribute(lstm_persist,
                         cudaFuncAttributeMaxDynamicSharedMemorySize, PSMEM_BYTES);

    const dim3 ggrid(G_ / BN, TB_ / BM);   // (32, 256)
    const int in_sel[L_]  = { 0, 0, 1, 0 };
    const int out_sel[L_] = { 0, 1, 0, 1 };

    for (int l = 0; l < L_; l++) {
        if (l == 0)
            gemm_gates_tc<true ><<<ggrid, 256>>>(x, Wih, bih, bhh, l, 0);
        else
            gemm_gates_tc<false><<<ggrid, 256>>>(nullptr, Wih, bih, bhh, l, in_sel[l]);
        lstm_persist<<<NBLK, NTHR, PSMEM_BYTES>>>(Whh, l, out_sel[l]);
    }
    fc_kernel<<<B_, 256>>>(fc_w, fc_b, out);
}

// round 7
// speedup vs baseline: 1.6960x; 1.5202x over previous
#include <cuda_runtime.h>
#include <math.h>
#include <stddef.h>
#include <stdint.h>
#include <mma.h>

using namespace nvcuda;

// Problem dims (fixed)
#define B_   64
#define T_   512
#define D_   1024
#define H_   1024
#define L_   4
#define G_   4096           // 4*H
#define O_   256
#define TB_  (T_ * B_)      // 32768

#define NBLK 128            // persistent-kernel grid
#define NTHR 256

// ---------------------------------------------------------------------------
// Device scratch (static globals — no allocation allowed)
// ---------------------------------------------------------------------------
__device__ float g_gates[(size_t)TB_ * G_];   // 512 MB: input-part of gates
__device__ float g_seq0[(size_t)TB_ * H_];    // 128 MB
__device__ float g_seq1[(size_t)TB_ * H_];    // 128 MB
__device__ float g_hA[B_ * H_];
__device__ float g_hB[B_ * H_];

__device__ unsigned g_bar_count = 0;
__device__ unsigned g_bar_gen   = 0;

// ---------------------------------------------------------------------------
// Software grid barrier (all NBLK blocks resident)
// ---------------------------------------------------------------------------
__device__ __forceinline__ void grid_barrier() {
    __threadfence();
    __syncthreads();
    if (threadIdx.x == 0) {
        unsigned gen = *(volatile unsigned*)&g_bar_gen;
        unsigned old = atomicAdd(&g_bar_count, 1u);
        if (old == NBLK - 1) {
            g_bar_count = 0;
            __threadfence();
            atomicAdd(&g_bar_gen, 1u);
        } else {
            while (*(volatile unsigned*)&g_bar_gen == gen) { }
        }
        __threadfence();
    }
    __syncthreads();
}

// ---------------------------------------------------------------------------
// cp.async helpers (sm_80-baseline PTX — safe for plain sm_103 target)
// ---------------------------------------------------------------------------
__device__ __forceinline__ uint32_t smem_u32(const void* p) {
    uint32_t a;
    asm("{ .reg .u64 t; cvta.to.shared.u64 t, %1; cvt.u32.u64 %0, t; }"
        : "=r"(a) : "l"(p));
    return a;
}
__device__ __forceinline__ void cp16(uint32_t dst, const void* src) {
    asm volatile("cp.async.cg.shared.global [%0], [%1], 16;"
                 :: "r"(dst), "l"(src));
}
__device__ __forceinline__ void cp_commit() {
    asm volatile("cp.async.commit_group;" ::: "memory");
}
template <int N>
__device__ __forceinline__ void cp_wait() {
    asm volatile("cp.async.wait_group %0;" :: "n"(N) : "memory");
}

// ===========================================================================
// WMMA tf32 input GEMM (unchanged from R5 — passing):
//   gates[m, n] = bias[n] + sum_k A[m,k] * W[n,k]      (C = A · Wᵀ)
// ===========================================================================
#define BM 128
#define BN 128
#define BK 16
#define APITCH 20                       // 80 B  (16B multiple ✓)
#define STG_FLOATS (BM * APITCH)
#define CPITCH 68                       // 272 B (16B multiple ✓)
#define GEMM_SM_FLOATS (4 * STG_FLOATS + 128)

template <bool LAYER0>
__device__ __forceinline__ void load_stage(float* As, float* Ws, int s, int c,
                                           const float* __restrict__ A,
                                           const float* __restrict__ W,
                                           int m0, int n0, int tid)
{
    const int k0 = c * BK;
    float* as = As + s * STG_FLOATS;
    float* ws = Ws + s * STG_FLOATS;
#pragma unroll
    for (int i = 0; i < 2; i++) {
        int idx = tid + i * 256;
        int row = idx >> 2, seg = idx & 3;
        const float* src;
        if (LAYER0) {
            int m = m0 + row;
            src = A + ((size_t)(m & 63) * T_ + (m >> 6)) * D_ + k0 + seg * 4;
        } else {
            src = A + (size_t)(m0 + row) * H_ + k0 + seg * 4;
        }
        cp16(smem_u32(&as[row * APITCH + seg * 4]), src);
    }
#pragma unroll
    for (int i = 0; i < 2; i++) {
        int idx = tid + i * 256;
        int row = idx >> 2, seg = idx & 3;
        cp16(smem_u32(&ws[row * APITCH + seg * 4]),
             W + (size_t)(n0 + row) * H_ + k0 + seg * 4);
    }
    cp_commit();
}

template <bool LAYER0>
__global__ void __launch_bounds__(256)
gemm_gates_tc(const float* __restrict__ x,
              const float* __restrict__ Wih_all,
              const float* __restrict__ bih_all,
              const float* __restrict__ bhh_all,
              int layer, int in_sel)
{
    __shared__ float sm[GEMM_SM_FLOATS];
    float* As    = sm;
    float* Ws    = sm + 2 * STG_FLOATS;
    float* biasS = sm + 4 * STG_FLOATS;
    float* Cbuf  = sm;

    const float* A = LAYER0 ? x : (in_sel == 0 ? g_seq0 : g_seq1);
    const float* W = Wih_all + (size_t)layer * G_ * H_;

    const int tid = threadIdx.x;
    const int n0  = blockIdx.x * BN;
    const int m0  = blockIdx.y * BM;
    const int wid = tid >> 5;
    const int wm  = wid & 3;
    const int wn  = wid >> 2;

    if (tid < 128)
        biasS[tid] = bih_all[(size_t)layer * G_ + n0 + tid]
                   + bhh_all[(size_t)layer * G_ + n0 + tid];

    wmma::fragment<wmma::accumulator, 16, 16, 8, float> cf[2][4];
#pragma unroll
    for (int i = 0; i < 2; i++)
#pragma unroll
        for (int j = 0; j < 4; j++) wmma::fill_fragment(cf[i][j], 0.0f);

    load_stage<LAYER0>(As, Ws, 0, 0, A, W, m0, n0, tid);

    const int NC = H_ / BK;
    for (int c = 0; c < NC; c++) {
        const int s = c & 1;
        if (c + 1 < NC) {
            load_stage<LAYER0>(As, Ws, s ^ 1, c + 1, A, W, m0, n0, tid);
            cp_wait<1>();
        } else {
            cp_wait<0>();
        }
        __syncthreads();

        const float* as = As + s * STG_FLOATS;
        const float* ws = Ws + s * STG_FLOATS;
#pragma unroll
        for (int kk = 0; kk < BK; kk += 8) {
            wmma::fragment<wmma::matrix_a, 16, 16, 8, wmma::precision::tf32,
                           wmma::row_major> af[2];
            wmma::fragment<wmma::matrix_b, 16, 16, 8, wmma::precision::tf32,
                           wmma::col_major> bf[4];
#pragma unroll
            for (int i = 0; i < 2; i++) {
                wmma::load_matrix_sync(af[i],
                    as + (wm * 32 + i * 16) * APITCH + kk, APITCH);
#pragma unroll
                for (int e = 0; e < af[i].num_elements; e++)
                    af[i].x[e] = wmma::__float_to_tf32(af[i].x[e]);
            }
#pragma unroll
            for (int j = 0; j < 4; j++) {
                wmma::load_matrix_sync(bf[j],
                    ws + (wn * 64 + j * 16) * APITCH + kk, APITCH);
#pragma unroll
                for (int e = 0; e < bf[j].num_elements; e++)
                    bf[j].x[e] = wmma::__float_to_tf32(bf[j].x[e]);
            }
#pragma unroll
            for (int i = 0; i < 2; i++)
#pragma unroll
                for (int j = 0; j < 4; j++)
                    wmma::mma_sync(cf[i][j], af[i], bf[j], cf[i][j]);
        }
        __syncthreads();
    }

#pragma unroll
    for (int half = 0; half < 2; half++) {
        if (wn == half) {
#pragma unroll
            for (int i = 0; i < 2; i++)
#pragma unroll
                for (int j = 0; j < 4; j++)
                    wmma::store_matrix_sync(
                        &Cbuf[(wm * 32 + i * 16) * CPITCH + j * 16],
                        cf[i][j], CPITCH, wmma::mem_row_major);
        }
        __syncthreads();
#pragma unroll
        for (int q = 0; q < 8; q++) {
            int lin = q * 256 + tid;
            int row = lin >> 4;
            int c4  = lin & 15;
            float4 v = *reinterpret_cast<const float4*>(&Cbuf[row * CPITCH + c4 * 4]);
            int n = half * 64 + c4 * 4;
            v.x += biasS[n + 0];
            v.y += biasS[n + 1];
            v.z += biasS[n + 2];
            v.w += biasS[n + 3];
            *reinterpret_cast<float4*>(
                &g_gates[(size_t)(m0 + row) * G_ + n0 + n]) = v;
        }
        __syncthreads();
    }
}

// ===========================================================================
// Persistent recurrent kernel, TENSOR-CORE edition (R6 design, pitches FIXED:
// all WMMA leading dimensions must be multiples of 4 floats / 16 bytes).
//   WP 1025 -> 1036   (4144 B = 259*16 ✓)
//   PP   33 -> 36     ( 144 B =   9*16 ✓)
// ===========================================================================
#define WP 1036                       // Ws pitch (16B multiple ✓)
#define HP 132                        // Hs pitch (528 B = 33*16 ✓)
#define PP 36                         // pre pitch (16B multiple ✓)
#define KCH 128                       // K-chunk
#define WS_FL  (32 * WP)              // 33152
#define HS_FL  (64 * HP)              // 8448 per buffer
#define PRE_FL (64 * PP)              // 2304
#define PSMEM_BYTES ((WS_FL + 2 * HS_FL + PRE_FL) * 4)   // 209,408 B

__device__ __forceinline__ void stage_h(float* dst, const float* hin,
                                        int ch, int tid)
{
#pragma unroll
    for (int i = 0; i < 8; i++) {
        int idx = tid + i * 256;
        int row = idx >> 5;           // 0..63
        int seg = idx & 31;           // 0..31 (x4 floats)
        cp16(smem_u32(dst + row * HP + seg * 4),
             hin + row * H_ + ch * KCH + seg * 4);
    }
    cp_commit();
}

__global__ void __launch_bounds__(NTHR, 1)
lstm_persist_tc(const float* __restrict__ Whh_all, int layer, int out_sel)
{
    extern __shared__ float smemf[];
    float* Ws  = smemf;                         // [c][k] col-major, pitch WP
    float* Hs  = smemf + WS_FL;                 // 2 x [64][HP]
    float* pre = smemf + WS_FL + 2 * HS_FL;     // [64][PP]

    const float* W      = Whh_all + (size_t)layer * G_ * H_;
    float*       seqout = (out_sel == 0) ? g_seq0 : g_seq1;

    const int jb  = blockIdx.x;
    const int tid = threadIdx.x;
    const int wid = tid >> 5;
    const int wm  = wid & 3;          // m-tile (16 batch rows)
    const int wn  = wid >> 2;         // n-tile (16 gate cols)

    const int eb  = tid >> 2;         // batch row for elementwise
    const int ejj = (tid & 3) * 2;
    const int jg0 = jb * 8 + ejj;

    // ---- stage Whh slice (tf32-converted) ----
    for (int i = tid; i < 32 * 1024; i += 256) {
        int c = i >> 10, k = i & 1023;
        int wrow = (c >> 3) * H_ + jb * 8 + (c & 7);
        Ws[c * WP + k] = wmma::__float_to_tf32(W[(size_t)wrow * H_ + k]);
    }

    // ---- zero initial h ----
    g_hA[jb * 512 + tid]       = 0.0f;
    g_hA[jb * 512 + 256 + tid] = 0.0f;

    float2 creg = make_float2(0.0f, 0.0f);

    grid_barrier();

    for (int t = 0; t < T_; t++) {
        const float* hin  = (t & 1) ? g_hB : g_hA;
        float*       hout = (t & 1) ? g_hA : g_hB;

        // input-gate contributions (DRAM latency hidden behind the K pipeline)
        const float* grow = g_gates + ((size_t)(t * B_ + eb)) * G_ + jg0;
        float2 G0 = *reinterpret_cast<const float2*>(grow);
        float2 G1 = *reinterpret_cast<const float2*>(grow + H_);
        float2 G2 = *reinterpret_cast<const float2*>(grow + 2 * H_);
        float2 G3 = *reinterpret_cast<const float2*>(grow + 3 * H_);

        wmma::fragment<wmma::accumulator, 16, 16, 8, float> cf;
        wmma::fill_fragment(cf, 0.0f);

        stage_h(Hs, hin, 0, tid);     // chunk 0 -> buffer 0

        for (int ch = 0; ch < H_ / KCH; ch++) {      // 8 chunks
            if (ch + 1 < H_ / KCH) {
                stage_h(Hs + ((ch + 1) & 1) * HS_FL, hin, ch + 1, tid);
                cp_wait<1>();
            } else {
                cp_wait<0>();
            }
            __syncthreads();

            const float* hb = Hs + (ch & 1) * HS_FL;
            const float* wb = Ws + (wn * 16) * WP + ch * KCH;
#pragma unroll
            for (int ks = 0; ks < KCH / 8; ks++) {   // 16 k-steps
                wmma::fragment<wmma::matrix_a, 16, 16, 8,
                               wmma::precision::tf32, wmma::row_major> af;
                wmma::fragment<wmma::matrix_b, 16, 16, 8,
                               wmma::precision::tf32, wmma::col_major> bf;
                // h was written tf32-rounded => raw bits are valid tf32
                wmma::load_matrix_sync(af, hb + (wm * 16) * HP + ks * 8, HP);
                wmma::load_matrix_sync(bf, wb + ks * 8, WP);
                wmma::mma_sync(cf, af, bf, cf);
            }
            __syncthreads();          // before next iteration overwrites buffer
        }

        // stage pre-activations
        wmma::store_matrix_sync(&pre[(wm * 16) * PP + wn * 16], cf, PP,
                                wmma::mem_row_major);
        __syncthreads();

        // elementwise: 2 cells per thread
        {
            const float* pr = &pre[eb * PP];
            float i0 = pr[ejj]      + G0.x, i1 = pr[ejj + 1]      + G0.y;
            float f0 = pr[8 + ejj]  + G1.x, f1 = pr[8 + ejj + 1]  + G1.y;
            float g0 = pr[16 + ejj] + G2.x, g1 = pr[16 + ejj + 1] + G2.y;
            float o0 = pr[24 + ejj] + G3.x, o1 = pr[24 + ejj + 1] + G3.y;
            i0 = 1.0f / (1.0f + __expf(-i0));
            i1 = 1.0f / (1.0f + __expf(-i1));
            f0 = 1.0f / (1.0f + __expf(-f0));
            f1 = 1.0f / (1.0f + __expf(-f1));
            o0 = 1.0f / (1.0f + __expf(-o0));
            o1 = 1.0f / (1.0f + __expf(-o1));
            g0 = tanhf(g0);
            g1 = tanhf(g1);
            creg.x = f0 * creg.x + i0 * g0;
            creg.y = f1 * creg.y + i1 * g1;
            float hx = o0 * tanhf(creg.x);
            float hy = o1 * tanhf(creg.y);
            // ping-pong h: tf32-rounded (feeds next step's MMA A operand)
            *reinterpret_cast<float2*>(&hout[eb * H_ + jg0]) =
                make_float2(wmma::__float_to_tf32(hx), wmma::__float_to_tf32(hy));
            // sequence output: full precision (feeds next layer's input GEMM)
            *reinterpret_cast<float2*>(&seqout[(size_t)(t * B_ + eb) * H_ + jg0]) =
                make_float2(hx, hy);
        }
        __syncthreads();              // pre reads done before next step's store

        grid_barrier();
    }
}

// ---------------------------------------------------------------------------
// Final FC (reads tf32-rounded final h — one extra rounding, negligible)
// ---------------------------------------------------------------------------
__global__ void __launch_bounds__(256)
fc_kernel(const float* __restrict__ fc_w, const float* __restrict__ fc_b,
          float* __restrict__ out)
{
    int b = blockIdx.x;
    int o = threadIdx.x;
    const float4* hv = reinterpret_cast<const float4*>(&g_hA[b * H_]);
    const float4* wv = reinterpret_cast<const float4*>(&fc_w[(size_t)o * H_]);
    float s = 0.0f;
#pragma unroll 8
    for (int k = 0; k < H_ / 4; k++) {
        float4 a = hv[k];
        float4 w = wv[k];
        s += a.x * w.x + a.y * w.y + a.z * w.z + a.w * w.w;
    }
    out[b * O_ + o] = s + fc_b[o];
}

// ---------------------------------------------------------------------------
// Launch: 9 graph nodes (4 wmma-GEMM + 4 persistent-TC + 1 FC)
// ---------------------------------------------------------------------------
extern "C" void kernel_launch(void* const* d_in, const int* in_sizes, int n_in,
                              void* d_out, int out_size)
{
    (void)in_sizes; (void)n_in; (void)out_size;
    const float* x    = (const float*)d_in[0];
    const float* Wih  = (const float*)d_in[1];
    const float* Whh  = (const float*)d_in[2];
    const float* bih  = (const float*)d_in[3];
    const float* bhh  = (const float*)d_in[4];
    const float* fc_w = (const float*)d_in[5];
    const float* fc_b = (const float*)d_in[6];
    float* out = (float*)d_out;

    cudaFuncSetAttribute(lstm_persist_tc,
                         cudaFuncAttributeMaxDynamicSharedMemorySize, PSMEM_BYTES);

    const dim3 ggrid(G_ / BN, TB_ / BM);   // (32, 256)
    const int in_sel[L_]  = { 0, 0, 1, 0 };
    const int out_sel[L_] = { 0, 1, 0, 1 };

    for (int l = 0; l < L_; l++) {
        if (l == 0)
            gemm_gates_tc<true ><<<ggrid, 256>>>(x, Wih, bih, bhh, l, 0);
        else
            gemm_gates_tc<false><<<ggrid, 256>>>(nullptr, Wih, bih, bhh, l, in_sel[l]);
        lstm_persist_tc<<<NBLK, NTHR, PSMEM_BYTES>>>(Whh, l, out_sel[l]);
    }
    fc_kernel<<<B_, 256>>>(fc_w, fc_b, out);
}

// round 8
// speedup vs baseline: 1.8376x; 1.0835x over previous
#include <cuda_runtime.h>
#include <math.h>
#include <stddef.h>
#include <stdint.h>
#include <mma.h>

using namespace nvcuda;

// Problem dims (fixed)
#define B_   64
#define T_   512
#define D_   1024
#define H_   1024
#define L_   4
#define G_   4096           // 4*H
#define O_   256
#define TB_  (T_ * B_)      // 32768

#define NBLK 128            // persistent-kernel grid
#define NTHR 256

// ---------------------------------------------------------------------------
// Device scratch (static globals — no allocation allowed)
// ---------------------------------------------------------------------------
__device__ float g_gates[(size_t)TB_ * G_];   // 512 MB: input-part of gates
__device__ float g_seq0[(size_t)TB_ * H_];    // 128 MB
__device__ float g_seq1[(size_t)TB_ * H_];    // 128 MB
__device__ float g_hA[B_ * H_];
__device__ float g_hB[B_ * H_];

__device__ unsigned g_bar_count = 0;
__device__ unsigned g_bar_gen   = 0;

// ---------------------------------------------------------------------------
// Software grid barrier (all NBLK blocks resident)
// ---------------------------------------------------------------------------
__device__ __forceinline__ void grid_barrier() {
    __threadfence();
    __syncthreads();
    if (threadIdx.x == 0) {
        unsigned gen = *(volatile unsigned*)&g_bar_gen;
        unsigned old = atomicAdd(&g_bar_count, 1u);
        if (old == NBLK - 1) {
            g_bar_count = 0;
            __threadfence();
            atomicAdd(&g_bar_gen, 1u);
        } else {
            while (*(volatile unsigned*)&g_bar_gen == gen) { }
        }
        __threadfence();
    }
    __syncthreads();
}

// ---------------------------------------------------------------------------
// cp.async helpers (sm_80-baseline PTX)
// ---------------------------------------------------------------------------
__device__ __forceinline__ uint32_t smem_u32(const void* p) {
    uint32_t a;
    asm("{ .reg .u64 t; cvta.to.shared.u64 t, %1; cvt.u32.u64 %0, t; }"
        : "=r"(a) : "l"(p));
    return a;
}
__device__ __forceinline__ void cp16(uint32_t dst, const void* src) {
    asm volatile("cp.async.cg.shared.global [%0], [%1], 16;"
                 :: "r"(dst), "l"(src));
}
__device__ __forceinline__ void cp_commit() {
    asm volatile("cp.async.commit_group;" ::: "memory");
}
template <int N>
__device__ __forceinline__ void cp_wait() {
    asm volatile("cp.async.wait_group %0;" :: "n"(N) : "memory");
}

// raw tf32 mma: D = A(16x8,row) * B(8x8,col) + D
__device__ __forceinline__ void mma8(float* c,
                                     float a0, float a1, float a2, float a3,
                                     float b0, float b1) {
    asm volatile(
        "mma.sync.aligned.m16n8k8.row.col.f32.tf32.tf32.f32 "
        "{%0,%1,%2,%3}, {%4,%5,%6,%7}, {%8,%9}, {%0,%1,%2,%3};"
        : "+f"(c[0]), "+f"(c[1]), "+f"(c[2]), "+f"(c[3])
        : "r"(__float_as_uint(a0)), "r"(__float_as_uint(a1)),
          "r"(__float_as_uint(a2)), "r"(__float_as_uint(a3)),
          "r"(__float_as_uint(b0)), "r"(__float_as_uint(b1)));
}

// ===========================================================================
// WMMA tf32 input GEMM (unchanged from R5/R7 — passing):
//   gates[m, n] = bias[n] + sum_k A[m,k] * W[n,k]      (C = A · Wᵀ)
// ===========================================================================
#define BM 128
#define BN 128
#define BK 16
#define APITCH 20
#define STG_FLOATS (BM * APITCH)
#define CPITCH 68
#define GEMM_SM_FLOATS (4 * STG_FLOATS + 128)

template <bool LAYER0>
__device__ __forceinline__ void load_stage(float* As, float* Ws, int s, int c,
                                           const float* __restrict__ A,
                                           const float* __restrict__ W,
                                           int m0, int n0, int tid)
{
    const int k0 = c * BK;
    float* as = As + s * STG_FLOATS;
    float* ws = Ws + s * STG_FLOATS;
#pragma unroll
    for (int i = 0; i < 2; i++) {
        int idx = tid + i * 256;
        int row = idx >> 2, seg = idx & 3;
        const float* src;
        if (LAYER0) {
            int m = m0 + row;
            src = A + ((size_t)(m & 63) * T_ + (m >> 6)) * D_ + k0 + seg * 4;
        } else {
            src = A + (size_t)(m0 + row) * H_ + k0 + seg * 4;
        }
        cp16(smem_u32(&as[row * APITCH + seg * 4]), src);
    }
#pragma unroll
    for (int i = 0; i < 2; i++) {
        int idx = tid + i * 256;
        int row = idx >> 2, seg = idx & 3;
        cp16(smem_u32(&ws[row * APITCH + seg * 4]),
             W + (size_t)(n0 + row) * H_ + k0 + seg * 4);
    }
    cp_commit();
}

template <bool LAYER0>
__global__ void __launch_bounds__(256)
gemm_gates_tc(const float* __restrict__ x,
              const float* __restrict__ Wih_all,
              const float* __restrict__ bih_all,
              const float* __restrict__ bhh_all,
              int layer, int in_sel)
{
    __shared__ float sm[GEMM_SM_FLOATS];
    float* As    = sm;
    float* Ws    = sm + 2 * STG_FLOATS;
    float* biasS = sm + 4 * STG_FLOATS;
    float* Cbuf  = sm;

    const float* A = LAYER0 ? x : (in_sel == 0 ? g_seq0 : g_seq1);
    const float* W = Wih_all + (size_t)layer * G_ * H_;

    const int tid = threadIdx.x;
    const int n0  = blockIdx.x * BN;
    const int m0  = blockIdx.y * BM;
    const int wid = tid >> 5;
    const int wm  = wid & 3;
    const int wn  = wid >> 2;

    if (tid < 128)
        biasS[tid] = bih_all[(size_t)layer * G_ + n0 + tid]
                   + bhh_all[(size_t)layer * G_ + n0 + tid];

    wmma::fragment<wmma::accumulator, 16, 16, 8, float> cf[2][4];
#pragma unroll
    for (int i = 0; i < 2; i++)
#pragma unroll
        for (int j = 0; j < 4; j++) wmma::fill_fragment(cf[i][j], 0.0f);

    load_stage<LAYER0>(As, Ws, 0, 0, A, W, m0, n0, tid);

    const int NC = H_ / BK;
    for (int c = 0; c < NC; c++) {
        const int s = c & 1;
        if (c + 1 < NC) {
            load_stage<LAYER0>(As, Ws, s ^ 1, c + 1, A, W, m0, n0, tid);
            cp_wait<1>();
        } else {
            cp_wait<0>();
        }
        __syncthreads();

        const float* as = As + s * STG_FLOATS;
        const float* ws = Ws + s * STG_FLOATS;
#pragma unroll
        for (int kk = 0; kk < BK; kk += 8) {
            wmma::fragment<wmma::matrix_a, 16, 16, 8, wmma::precision::tf32,
                           wmma::row_major> af[2];
            wmma::fragment<wmma::matrix_b, 16, 16, 8, wmma::precision::tf32,
                           wmma::col_major> bf[4];
#pragma unroll
            for (int i = 0; i < 2; i++) {
                wmma::load_matrix_sync(af[i],
                    as + (wm * 32 + i * 16) * APITCH + kk, APITCH);
#pragma unroll
                for (int e = 0; e < af[i].num_elements; e++)
                    af[i].x[e] = wmma::__float_to_tf32(af[i].x[e]);
            }
#pragma unroll
            for (int j = 0; j < 4; j++) {
                wmma::load_matrix_sync(bf[j],
                    ws + (wn * 64 + j * 16) * APITCH + kk, APITCH);
#pragma unroll
                for (int e = 0; e < bf[j].num_elements; e++)
                    bf[j].x[e] = wmma::__float_to_tf32(bf[j].x[e]);
            }
#pragma unroll
            for (int i = 0; i < 2; i++)
#pragma unroll
                for (int j = 0; j < 4; j++)
                    wmma::mma_sync(cf[i][j], af[i], bf[j], cf[i][j]);
        }
        __syncthreads();
    }

#pragma unroll
    for (int half = 0; half < 2; half++) {
        if (wn == half) {
#pragma unroll
            for (int i = 0; i < 2; i++)
#pragma unroll
                for (int j = 0; j < 4; j++)
                    wmma::store_matrix_sync(
                        &Cbuf[(wm * 32 + i * 16) * CPITCH + j * 16],
                        cf[i][j], CPITCH, wmma::mem_row_major);
        }
        __syncthreads();
#pragma unroll
        for (int q = 0; q < 8; q++) {
            int lin = q * 256 + tid;
            int row = lin >> 4;
            int c4  = lin & 15;
            float4 v = *reinterpret_cast<const float4*>(&Cbuf[row * CPITCH + c4 * 4]);
            int n = half * 64 + c4 * 4;
            v.x += biasS[n + 0];
            v.y += biasS[n + 1];
            v.z += biasS[n + 2];
            v.w += biasS[n + 3];
            *reinterpret_cast<float4*>(
                &g_gates[(size_t)(m0 + row) * G_ + n0 + n]) = v;
        }
        __syncthreads();
    }
}

// ===========================================================================
// Persistent recurrent kernel v3: raw mma.sync tf32, A (h) fragments loaded
// DIRECTLY from global with __ldcg (no cp.async staging — that was the 18µs/
// step bottleneck at 8cyc/LDGSTS), B (Whh) pre-packed in SMEM in fragment
// layout (one conflict-free LDS.128 per k16 per n-tile).
//
// 8 warps = 4 m-tiles (16 batch rows) x 2 K-halves (512 each).
// Each warp covers ALL 4 n-tiles (gates) => no duplicate h reads.
// K-split partials reduced through SMEM in the elementwise phase.
// ===========================================================================
#define PP 36                                  // pre pitch (16B multiple)
#define PRE_FL (64 * PP)                       // 2304 floats per partial
#define WPK_FL (32 * 1024)                     // 32768 floats (131 KB)
#define PSMEM_BYTES ((WPK_FL + 2 * PRE_FL) * 4)   // 149,504 B

__global__ void __launch_bounds__(NTHR, 1)
lstm_persist_tc(const float* __restrict__ Whh_all, int layer, int out_sel)
{
    extern __shared__ float smemf[];
    float* Wpack = smemf;                      // fragment-layout Whh slice
    float* preS  = smemf + WPK_FL;             // 2 x [64][PP] k-split partials

    const float* W      = Whh_all + (size_t)layer * G_ * H_;
    float*       seqout = (out_sel == 0) ? g_seq0 : g_seq1;

    const int jb   = blockIdx.x;
    const int tid  = threadIdx.x;
    const int lane = tid & 31;
    const int wid  = tid >> 5;
    const int wm   = wid & 3;        // m-tile: rows [wm*16, wm*16+16)
    const int ks   = wid >> 2;       // K half: 0 or 1
    const int grp  = lane >> 2;      // 0..7
    const int tq   = lane & 3;       // 0..3

    const int eb  = tid >> 2;        // batch row for elementwise
    const int ejj = (tid & 3) * 2;
    const int jg0 = jb * 8 + ejj;

    // ---- pack Whh slice into mma-fragment layout (tf32-rounded) ----
    // Wpack[((k16*4 + nt)*32 + lane)*4 + j], j = {b0(k8a), b1(k8a), b0(k8b), b1(k8b)}
    //   b0(k8) = W[nt*H + jb*8 + (lane>>2)][k8*8 + (lane&3)]
    //   b1(k8) = same row, col +4
    for (int i = tid; i < WPK_FL; i += NTHR) {
        int j   = i & 3;
        int ln  = (i >> 2) & 31;
        int nt  = (i >> 7) & 3;
        int k16 = i >> 9;                       // 0..63
        int k8  = k16 * 2 + (j >> 1);
        int kc  = k8 * 8 + (ln & 3) + (j & 1) * 4;
        int wr  = nt * H_ + jb * 8 + (ln >> 2);
        Wpack[i] = wmma::__float_to_tf32(W[(size_t)wr * H_ + kc]);
    }

    // ---- zero initial h ----
    g_hA[jb * 512 + tid]       = 0.0f;
    g_hA[jb * 512 + 256 + tid] = 0.0f;

    float2 creg = make_float2(0.0f, 0.0f);

    grid_barrier();

    for (int t = 0; t < T_; t++) {
        const float* hin  = (t & 1) ? g_hB : g_hA;
        float*       hout = (t & 1) ? g_hA : g_hB;

        // input-gate contributions (latency hidden behind the K loop)
        const float* grow = g_gates + ((size_t)(t * B_ + eb)) * G_ + jg0;
        float2 G0 = *reinterpret_cast<const float2*>(grow);
        float2 G1 = *reinterpret_cast<const float2*>(grow + H_);
        float2 G2 = *reinterpret_cast<const float2*>(grow + 2 * H_);
        float2 G3 = *reinterpret_cast<const float2*>(grow + 3 * H_);

        float acc[4][4];
#pragma unroll
        for (int nt = 0; nt < 4; nt++)
#pragma unroll
            for (int r = 0; r < 4; r++) acc[nt][r] = 0.0f;

        // A row pointers (h is tf32-rounded in the ping-pong buffers)
        const float* hr0 = hin + (wm * 16 + grp) * H_ + ks * 512;
        const float* hr1 = hr0 + 8 * H_;

#pragma unroll 2
        for (int k16 = 0; k16 < 32; k16++) {
            const int k = k16 * 16 + tq;
            float a0 = __ldcg(hr0 + k),      a1 = __ldcg(hr1 + k);
            float a2 = __ldcg(hr0 + k + 4),  a3 = __ldcg(hr1 + k + 4);
            float a4 = __ldcg(hr0 + k + 8),  a5 = __ldcg(hr1 + k + 8);
            float a6 = __ldcg(hr0 + k + 12), a7 = __ldcg(hr1 + k + 12);
            const int kk = ks * 32 + k16;
#pragma unroll
            for (int nt = 0; nt < 4; nt++) {
                float4 b = *reinterpret_cast<const float4*>(
                    &Wpack[((kk * 4 + nt) * 32 + lane) * 4]);
                mma8(acc[nt], a0, a1, a2, a3, b.x, b.y);
                mma8(acc[nt], a4, a5, a6, a7, b.z, b.w);
            }
        }

        // stage k-split partials:  c0,c1 -> (row, 2tq..), c2,c3 -> (row+8, ..)
        {
            float* pr = preS + ks * PRE_FL;
            const int rm = wm * 16 + grp;
#pragma unroll
            for (int nt = 0; nt < 4; nt++) {
                const int cn = nt * 8 + 2 * tq;
                *reinterpret_cast<float2*>(&pr[rm * PP + cn]) =
                    make_float2(acc[nt][0], acc[nt][1]);
                *reinterpret_cast<float2*>(&pr[(rm + 8) * PP + cn]) =
                    make_float2(acc[nt][2], acc[nt][3]);
            }
        }
        __syncthreads();

        // elementwise: 2 cells per thread, summing the two k-split partials
        {
            const float* p0 = &preS[eb * PP];
            const float* p1 = &preS[PRE_FL + eb * PP];
            float i0 = p0[ejj]      + p1[ejj]      + G0.x;
            float i1 = p0[ejj + 1]  + p1[ejj + 1]  + G0.y;
            float f0 = p0[8 + ejj]  + p1[8 + ejj]  + G1.x;
            float f1 = p0[9 + ejj]  + p1[9 + ejj]  + G1.y;
            float g0 = p0[16 + ejj] + p1[16 + ejj] + G2.x;
            float g1 = p0[17 + ejj] + p1[17 + ejj] + G2.y;
            float o0 = p0[24 + ejj] + p1[24 + ejj] + G3.x;
            float o1 = p0[25 + ejj] + p1[25 + ejj] + G3.y;
            i0 = 1.0f / (1.0f + __expf(-i0));
            i1 = 1.0f / (1.0f + __expf(-i1));
            f0 = 1.0f / (1.0f + __expf(-f0));
            f1 = 1.0f / (1.0f + __expf(-f1));
            o0 = 1.0f / (1.0f + __expf(-o0));
            o1 = 1.0f / (1.0f + __expf(-o1));
            g0 = tanhf(g0);
            g1 = tanhf(g1);
            creg.x = f0 * creg.x + i0 * g0;
            creg.y = f1 * creg.y + i1 * g1;
            float hx = o0 * tanhf(creg.x);
            float hy = o1 * tanhf(creg.y);
            // ping-pong h: tf32-rounded (next step's A operand reads raw bits)
            *reinterpret_cast<float2*>(&hout[eb * H_ + jg0]) =
                make_float2(wmma::__float_to_tf32(hx), wmma::__float_to_tf32(hy));
            // sequence output: full precision (next layer's input GEMM)
            *reinterpret_cast<float2*>(&seqout[(size_t)(t * B_ + eb) * H_ + jg0]) =
                make_float2(hx, hy);
        }

        grid_barrier();   // entry __syncthreads also protects preS reuse
    }
}

// ---------------------------------------------------------------------------
// Final FC (reads tf32-rounded final h — one extra rounding, negligible)
// ---------------------------------------------------------------------------
__global__ void __launch_bounds__(256)
fc_kernel(const float* __restrict__ fc_w, const float* __restrict__ fc_b,
          float* __restrict__ out)
{
    int b = blockIdx.x;
    int o = threadIdx.x;
    const float4* hv = reinterpret_cast<const float4*>(&g_hA[b * H_]);
    const float4* wv = reinterpret_cast<const float4*>(&fc_w[(size_t)o * H_]);
    float s = 0.0f;
#pragma unroll 8
    for (int k = 0; k < H_ / 4; k++) {
        float4 a = hv[k];
        float4 w = wv[k];
        s += a.x * w.x + a.y * w.y + a.z * w.z + a.w * w.w;
    }
    out[b * O_ + o] = s + fc_b[o];
}

// ---------------------------------------------------------------------------
// Launch: 9 graph nodes (4 wmma-GEMM + 4 persistent-TC + 1 FC)
// ---------------------------------------------------------------------------
extern "C" void kernel_launch(void* const* d_in, const int* in_sizes, int n_in,
                              void* d_out, int out_size)
{
    (void)in_sizes; (void)n_in; (void)out_size;
    const float* x    = (const float*)d_in[0];
    const float* Wih  = (const float*)d_in[1];
    const float* Whh  = (const float*)d_in[2];
    const float* bih  = (const float*)d_in[3];
    const float* bhh  = (const float*)d_in[4];
    const float* fc_w = (const float*)d_in[5];
    const float* fc_b = (const float*)d_in[6];
    float* out = (float*)d_out;

    cudaFuncSetAttribute(lstm_persist_tc,
                         cudaFuncAttributeMaxDynamicSharedMemorySize, PSMEM_BYTES);

    const dim3 ggrid(G_ / BN, TB_ / BM);   // (32, 256)
    const int in_sel[L_]  = { 0, 0, 1, 0 };
    const int out_sel[L_] = { 0, 1, 0, 1 };

    for (int l = 0; l < L_; l++) {
        if (l == 0)
            gemm_gates_tc<true ><<<ggrid, 256>>>(x, Wih, bih, bhh, l, 0);
        else
            gemm_gates_tc<false><<<ggrid, 256>>>(nullptr, Wih, bih, bhh, l, in_sel[l]);
        lstm_persist_tc<<<NBLK, NTHR, PSMEM_BYTES>>>(Whh, l, out_sel[l]);
    }
    fc_kernel<<<B_, 256>>>(fc_w, fc_b, out);
}

// round 10
// speedup vs baseline: 1.9284x; 1.0494x over previous
#include <cuda_runtime.h>
#include <math.h>
#include <stddef.h>
#include <stdint.h>
#include <mma.h>

using namespace nvcuda;

// Problem dims (fixed)
#define B_   64
#define T_   512
#define D_   1024
#define H_   1024
#define L_   4
#define G_   4096           // 4*H
#define O_   256
#define TB_  (T_ * B_)      // 32768

#define NBLK 128            // persistent-kernel grid
#define NTHR 256

// ---------------------------------------------------------------------------
// Device scratch (static globals — no allocation allowed)
// ---------------------------------------------------------------------------
__device__ float g_gates[(size_t)TB_ * G_];   // 512 MB: input-part of gates
__device__ float g_seq0[(size_t)TB_ * H_];    // 128 MB
__device__ float g_seq1[(size_t)TB_ * H_];    // 128 MB
__device__ float g_hA[B_ * H_];
__device__ float g_hB[B_ * H_];

__device__ unsigned g_bar_count = 0;
__device__ unsigned g_bar_gen   = 0;

// ---------------------------------------------------------------------------
// Software grid barrier (all NBLK blocks resident)
// ---------------------------------------------------------------------------
__device__ __forceinline__ void grid_barrier() {
    __threadfence();
    __syncthreads();
    if (threadIdx.x == 0) {
        unsigned gen = *(volatile unsigned*)&g_bar_gen;
        unsigned old = atomicAdd(&g_bar_count, 1u);
        if (old == NBLK - 1) {
            g_bar_count = 0;
            __threadfence();
            atomicAdd(&g_bar_gen, 1u);
        } else {
            while (*(volatile unsigned*)&g_bar_gen == gen) { }
        }
        __threadfence();
    }
    __syncthreads();
}

// ---------------------------------------------------------------------------
// cp.async helpers (sm_80-baseline PTX)
// ---------------------------------------------------------------------------
__device__ __forceinline__ uint32_t smem_u32(const void* p) {
    uint32_t a;
    asm("{ .reg .u64 t; cvta.to.shared.u64 t, %1; cvt.u32.u64 %0, t; }"
        : "=r"(a) : "l"(p));
    return a;
}
__device__ __forceinline__ void cp16(uint32_t dst, const void* src) {
    asm volatile("cp.async.cg.shared.global [%0], [%1], 16;"
                 :: "r"(dst), "l"(src));
}
__device__ __forceinline__ void cp_commit() {
    asm volatile("cp.async.commit_group;" ::: "memory");
}
template <int N>
__device__ __forceinline__ void cp_wait() {
    asm volatile("cp.async.wait_group %0;" :: "n"(N) : "memory");
}

// raw tf32 mma: D = A(16x8,row) * B(8x8,col) + D
__device__ __forceinline__ void mma8(float* c,
                                     float a0, float a1, float a2, float a3,
                                     float b0, float b1) {
    asm volatile(
        "mma.sync.aligned.m16n8k8.row.col.f32.tf32.tf32.f32 "
        "{%0,%1,%2,%3}, {%4,%5,%6,%7}, {%8,%9}, {%0,%1,%2,%3};"
        : "+f"(c[0]), "+f"(c[1]), "+f"(c[2]), "+f"(c[3])
        : "r"(__float_as_uint(a0)), "r"(__float_as_uint(a1)),
          "r"(__float_as_uint(a2)), "r"(__float_as_uint(a3)),
          "r"(__float_as_uint(b0)), "r"(__float_as_uint(b1)));
}

// ===========================================================================
// WMMA tf32 input GEMM (unchanged — passing):
//   gates[m, n] = bias[n] + sum_k A[m,k] * W[n,k]      (C = A · Wᵀ)
// ===========================================================================
#define BM 128
#define BN 128
#define BK 16
#define APITCH 20
#define STG_FLOATS (BM * APITCH)
#define CPITCH 68
#define GEMM_SM_FLOATS (4 * STG_FLOATS + 128)

template <bool LAYER0>
__device__ __forceinline__ void load_stage(float* As, float* Ws, int s, int c,
                                           const float* __restrict__ A,
                                           const float* __restrict__ W,
                                           int m0, int n0, int tid)
{
    const int k0 = c * BK;
    float* as = As + s * STG_FLOATS;
    float* ws = Ws + s * STG_FLOATS;
#pragma unroll
    for (int i = 0; i < 2; i++) {
        int idx = tid + i * 256;
        int row = idx >> 2, seg = idx & 3;
        const float* src;
        if (LAYER0) {
            int m = m0 + row;
            src = A + ((size_t)(m & 63) * T_ + (m >> 6)) * D_ + k0 + seg * 4;
        } else {
            src = A + (size_t)(m0 + row) * H_ + k0 + seg * 4;
        }
        cp16(smem_u32(&as[row * APITCH + seg * 4]), src);
    }
#pragma unroll
    for (int i = 0; i < 2; i++) {
        int idx = tid + i * 256;
        int row = idx >> 2, seg = idx & 3;
        cp16(smem_u32(&ws[row * APITCH + seg * 4]),
             W + (size_t)(n0 + row) * H_ + k0 + seg * 4);
    }
    cp_commit();
}

template <bool LAYER0>
__global__ void __launch_bounds__(256)
gemm_gates_tc(const float* __restrict__ x,
              const float* __restrict__ Wih_all,
              const float* __restrict__ bih_all,
              const float* __restrict__ bhh_all,
              int layer, int in_sel)
{
    __shared__ float sm[GEMM_SM_FLOATS];
    float* As    = sm;
    float* Ws    = sm + 2 * STG_FLOATS;
    float* biasS = sm + 4 * STG_FLOATS;
    float* Cbuf  = sm;

    const float* A = LAYER0 ? x : (in_sel == 0 ? g_seq0 : g_seq1);
    const float* W = Wih_all + (size_t)layer * G_ * H_;

    const int tid = threadIdx.x;
    const int n0  = blockIdx.x * BN;
    const int m0  = blockIdx.y * BM;
    const int wid = tid >> 5;
    const int wm  = wid & 3;
    const int wn  = wid >> 2;

    if (tid < 128)
        biasS[tid] = bih_all[(size_t)layer * G_ + n0 + tid]
                   + bhh_all[(size_t)layer * G_ + n0 + tid];

    wmma::fragment<wmma::accumulator, 16, 16, 8, float> cf[2][4];
#pragma unroll
    for (int i = 0; i < 2; i++)
#pragma unroll
        for (int j = 0; j < 4; j++) wmma::fill_fragment(cf[i][j], 0.0f);

    load_stage<LAYER0>(As, Ws, 0, 0, A, W, m0, n0, tid);

    const int NC = H_ / BK;
    for (int c = 0; c < NC; c++) {
        const int s = c & 1;
        if (c + 1 < NC) {
            load_stage<LAYER0>(As, Ws, s ^ 1, c + 1, A, W, m0, n0, tid);
            cp_wait<1>();
        } else {
            cp_wait<0>();
        }
        __syncthreads();

        const float* as = As + s * STG_FLOATS;
        const float* ws = Ws + s * STG_FLOATS;
#pragma unroll
        for (int kk = 0; kk < BK; kk += 8) {
            wmma::fragment<wmma::matrix_a, 16, 16, 8, wmma::precision::tf32,
                           wmma::row_major> af[2];
            wmma::fragment<wmma::matrix_b, 16, 16, 8, wmma::precision::tf32,
                           wmma::col_major> bf[4];
#pragma unroll
            for (int i = 0; i < 2; i++) {
                wmma::load_matrix_sync(af[i],
                    as + (wm * 32 + i * 16) * APITCH + kk, APITCH);
#pragma unroll
                for (int e = 0; e < af[i].num_elements; e++)
                    af[i].x[e] = wmma::__float_to_tf32(af[i].x[e]);
            }
#pragma unroll
            for (int j = 0; j < 4; j++) {
                wmma::load_matrix_sync(bf[j],
                    ws + (wn * 64 + j * 16) * APITCH + kk, APITCH);
#pragma unroll
                for (int e = 0; e < bf[j].num_elements; e++)
                    bf[j].x[e] = wmma::__float_to_tf32(bf[j].x[e]);
            }
#pragma unroll
            for (int i = 0; i < 2; i++)
#pragma unroll
                for (int j = 0; j < 4; j++)
                    wmma::mma_sync(cf[i][j], af[i], bf[j], cf[i][j]);
        }
        __syncthreads();
    }

#pragma unroll
    for (int half = 0; half < 2; half++) {
        if (wn == half) {
#pragma unroll
            for (int i = 0; i < 2; i++)
#pragma unroll
                for (int j = 0; j < 4; j++)
                    wmma::store_matrix_sync(
                        &Cbuf[(wm * 32 + i * 16) * CPITCH + j * 16],
                        cf[i][j], CPITCH, wmma::mem_row_major);
        }
        __syncthreads();
#pragma unroll
        for (int q = 0; q < 8; q++) {
            int lin = q * 256 + tid;
            int row = lin >> 4;
            int c4  = lin & 15;
            float4 v = *reinterpret_cast<const float4*>(&Cbuf[row * CPITCH + c4 * 4]);
            int n = half * 64 + c4 * 4;
            v.x += biasS[n + 0];
            v.y += biasS[n + 1];
            v.z += biasS[n + 2];
            v.w += biasS[n + 3];
            *reinterpret_cast<float4*>(
                &g_gates[(size_t)(m0 + row) * G_ + n0 + n]) = v;
        }
        __syncthreads();
    }
}

// ===========================================================================
// Persistent recurrent kernel v4: Whh ENTIRELY IN REGISTERS.
// 8 warps = 8 K-eighths (128 k each); each warp covers all 64 batch rows
// (4 m-frags) and all 32 gate cols (4 n-frags). B-fragments (16 k8 x 4 nt
// x 2 = 128 regs/thread) loaded once per layer from global in mma layout.
// Mainloop: pure __ldcg A-bursts + mma — NO shared memory, NO syncs.
// 8 K-split partials reduced through SMEM in the elementwise phase.
// ===========================================================================
#define PP 36                                  // pre pitch floats
#define PRE_FL (64 * PP)                       // 2304
#define NPART 8
#define PSMEM_BYTES (NPART * PRE_FL * 4)       // 73,728 B

__global__ void __launch_bounds__(NTHR, 1)
lstm_persist_tc(const float* __restrict__ Whh_all, int layer, int out_sel)
{
    extern __shared__ float preS[];            // [8][64][PP]

    const float* W      = Whh_all + (size_t)layer * G_ * H_;
    float*       seqout = (out_sel == 0) ? g_seq0 : g_seq1;

    const int jb   = blockIdx.x;
    const int tid  = threadIdx.x;
    const int lane = tid & 31;
    const int wid  = tid >> 5;       // K-eighth: k in [wid*128, wid*128+128)
    const int grp  = lane >> 2;      // 0..7
    const int tq   = lane & 3;       // 0..3

    const int eb  = tid >> 2;        // batch row for elementwise
    const int ejj = (tid & 3) * 2;
    const int jg0 = jb * 8 + ejj;

    // ---- Whh B-fragments -> registers (once per layer), tf32-rounded ----
    // bw[k8][nt][j]: b_j for mma k8 within my K-eighth, gate nt.
    //   b0 = W[nt*H + jb*8 + grp][wid*128 + k8*8 + tq], b1 = same +4
    float bw[16][4][2];
    {
        const float* wb = W + (size_t)(jb * 8 + grp) * H_ + wid * 128 + tq;
#pragma unroll
        for (int nt = 0; nt < 4; nt++) {
            const float* wr = wb + (size_t)nt * H_ * H_;
#pragma unroll
            for (int k8 = 0; k8 < 16; k8++) {
                bw[k8][nt][0] = wmma::__float_to_tf32(wr[k8 * 8]);
                bw[k8][nt][1] = wmma::__float_to_tf32(wr[k8 * 8 + 4]);
            }
        }
    }

    // ---- zero initial h ----
    g_hA[jb * 512 + tid]       = 0.0f;
    g_hA[jb * 512 + 256 + tid] = 0.0f;

    float2 creg = make_float2(0.0f, 0.0f);

    grid_barrier();

    for (int t = 0; t < T_; t++) {
        const float* hin  = (t & 1) ? g_hB : g_hA;
        float*       hout = (t & 1) ? g_hA : g_hB;

        // input-gate contributions (latency hidden behind the K loop)
        const float* grow = g_gates + ((size_t)(t * B_ + eb)) * G_ + jg0;
        float2 G0 = *reinterpret_cast<const float2*>(grow);
        float2 G1 = *reinterpret_cast<const float2*>(grow + H_);
        float2 G2 = *reinterpret_cast<const float2*>(grow + 2 * H_);
        float2 G3 = *reinterpret_cast<const float2*>(grow + 3 * H_);

        float acc[4][4][4];              // [m-frag][gate][c-regs]
#pragma unroll
        for (int mf = 0; mf < 4; mf++)
#pragma unroll
            for (int nt = 0; nt < 4; nt++)
#pragma unroll
                for (int r = 0; r < 4; r++) acc[mf][nt][r] = 0.0f;

        const float* hw = hin + wid * 128 + tq;   // my K-eighth, my tq

#pragma unroll
        for (int i = 0; i < 8; i++) {             // 8 k16 steps in my eighth
            const int kb = i * 16;
#pragma unroll
            for (int mf = 0; mf < 4; mf++) {
                const float* r0 = hw + (mf * 16 + grp) * H_ + kb;
                const float* r1 = r0 + 8 * H_;
                // 8 independent L2 loads (batch for MLP)
                float a0 = __ldcg(r0),      a1 = __ldcg(r1);
                float a2 = __ldcg(r0 + 4),  a3 = __ldcg(r1 + 4);
                float a4 = __ldcg(r0 + 8),  a5 = __ldcg(r1 + 8);
                float a6 = __ldcg(r0 + 12), a7 = __ldcg(r1 + 12);
#pragma unroll
                for (int nt = 0; nt < 4; nt++) {
                    mma8(acc[mf][nt], a0, a1, a2, a3,
                         bw[2 * i][nt][0], bw[2 * i][nt][1]);
                    mma8(acc[mf][nt], a4, a5, a6, a7,
                         bw[2 * i + 1][nt][0], bw[2 * i + 1][nt][1]);
                }
            }
        }

        // stage my K-split partial
        {
            float* pr = preS + wid * PRE_FL;
#pragma unroll
            for (int mf = 0; mf < 4; mf++) {
                const int rm = mf * 16 + grp;
#pragma unroll
                for (int nt = 0; nt < 4; nt++) {
                    const int cn = nt * 8 + 2 * tq;
                    *reinterpret_cast<float2*>(&pr[rm * PP + cn]) =
                        make_float2(acc[mf][nt][0], acc[mf][nt][1]);
                    *reinterpret_cast<float2*>(&pr[(rm + 8) * PP + cn]) =
                        make_float2(acc[mf][nt][2], acc[mf][nt][3]);
                }
            }
        }
        __syncthreads();

        // elementwise: 2 cells per thread, summing the 8 K-split partials
        {
            float i0 = G0.x, i1 = G0.y, f0 = G1.x, f1 = G1.y;
            float g0 = G2.x, g1 = G2.y, o0 = G3.x, o1 = G3.y;
#pragma unroll
            for (int p = 0; p < NPART; p++) {
                const float* pr = preS + p * PRE_FL + eb * PP;
                float2 v;
                v = *reinterpret_cast<const float2*>(&pr[ejj]);
                i0 += v.x; i1 += v.y;
                v = *reinterpret_cast<const float2*>(&pr[8 + ejj]);
                f0 += v.x; f1 += v.y;
                v = *reinterpret_cast<const float2*>(&pr[16 + ejj]);
                g0 += v.x; g1 += v.y;
                v = *reinterpret_cast<const float2*>(&pr[24 + ejj]);
                o0 += v.x; o1 += v.y;
            }
            i0 = 1.0f / (1.0f + __expf(-i0));
            i1 = 1.0f / (1.0f + __expf(-i1));
            f0 = 1.0f / (1.0f + __expf(-f0));
            f1 = 1.0f / (1.0f + __expf(-f1));
            o0 = 1.0f / (1.0f + __expf(-o0));
            o1 = 1.0f / (1.0f + __expf(-o1));
            g0 = tanhf(g0);
            g1 = tanhf(g1);
            creg.x = f0 * creg.x + i0 * g0;
            creg.y = f1 * creg.y + i1 * g1;
            float hx = o0 * tanhf(creg.x);
            float hy = o1 * tanhf(creg.y);
            // ping-pong h: tf32-rounded (next step's A operand reads raw bits)
            *reinterpret_cast<float2*>(&hout[eb * H_ + jg0]) =
                make_float2(wmma::__float_to_tf32(hx), wmma::__float_to_tf32(hy));
            // sequence output: full precision (next layer's input GEMM)
            *reinterpret_cast<float2*>(&seqout[(size_t)(t * B_ + eb) * H_ + jg0]) =
                make_float2(hx, hy);
        }

        grid_barrier();   // entry __syncthreads also protects preS reuse
    }
}

// ---------------------------------------------------------------------------
// Final FC (reads tf32-rounded final h — one extra rounding, negligible)
// ---------------------------------------------------------------------------
__global__ void __launch_bounds__(256)
fc_kernel(const float* __restrict__ fc_w, const float* __restrict__ fc_b,
          float* __restrict__ out)
{
    int b = blockIdx.x;
    int o = threadIdx.x;
    const float4* hv = reinterpret_cast<const float4*>(&g_hA[b * H_]);
    const float4* wv = reinterpret_cast<const float4*>(&fc_w[(size_t)o * H_]);
    float s = 0.0f;
#pragma unroll 8
    for (int k = 0; k < H_ / 4; k++) {
        float4 a = hv[k];
        float4 w = wv[k];
        s += a.x * w.x + a.y * w.y + a.z * w.z + a.w * w.w;
    }
    out[b * O_ + o] = s + fc_b[o];
}

// ---------------------------------------------------------------------------
// Launch: 9 graph nodes (4 wmma-GEMM + 4 persistent-TC + 1 FC)
// ---------------------------------------------------------------------------
extern "C" void kernel_launch(void* const* d_in, const int* in_sizes, int n_in,
                              void* d_out, int out_size)
{
    (void)in_sizes; (void)n_in; (void)out_size;
    const float* x    = (const float*)d_in[0];
    const float* Wih  = (const float*)d_in[1];
    const float* Whh  = (const float*)d_in[2];
    const float* bih  = (const float*)d_in[3];
    const float* bhh  = (const float*)d_in[4];
    const float* fc_w = (const float*)d_in[5];
    const float* fc_b = (const float*)d_in[6];
    float* out = (float*)d_out;

    cudaFuncSetAttribute(lstm_persist_tc,
                         cudaFuncAttributeMaxDynamicSharedMemorySize, PSMEM_BYTES);

    const dim3 ggrid(G_ / BN, TB_ / BM);   // (32, 256)
    const int in_sel[L_]  = { 0, 0, 1, 0 };
    const int out_sel[L_] = { 0, 1, 0, 1 };

    for (int l = 0; l < L_; l++) {
        if (l == 0)
            gemm_gates_tc<true ><<<ggrid, 256>>>(x, Wih, bih, bhh, l, 0);
        else
            gemm_gates_tc<false><<<ggrid, 256>>>(nullptr, Wih, bih, bhh, l, in_sel[l]);
        lstm_persist_tc<<<NBLK, NTHR, PSMEM_BYTES>>>(Whh, l, out_sel[l]);
    }
    fc_kernel<<<B_, 256>>>(fc_w, fc_b, out);
}

// round 11
// speedup vs baseline: 2.5407x; 1.3175x over previous
#include <cuda_runtime.h>
#include <cuda_fp16.h>
#include <math.h>
#include <stddef.h>
#include <stdint.h>
#include <mma.h>

using namespace nvcuda;

// Problem dims (fixed)
#define B_   64
#define T_   512
#define D_   1024
#define H_   1024
#define L_   4
#define G_   4096           // 4*H
#define O_   256
#define TB_  (T_ * B_)      // 32768

#define NBLK 128            // persistent-kernel grid
#define NTHR 256

// ---------------------------------------------------------------------------
// Device scratch (static globals — no allocation allowed)
// ---------------------------------------------------------------------------
__device__ float  g_gates[(size_t)TB_ * G_];  // 512 MB: input-part of gates
__device__ float  g_seq0[(size_t)TB_ * H_];   // 128 MB
__device__ float  g_seq1[(size_t)TB_ * H_];   // 128 MB
__device__ __half g_hA[B_ * H_];              // fp16 h ping
__device__ __half g_hB[B_ * H_];              // fp16 h pong

__device__ unsigned g_bar_count = 0;
__device__ unsigned g_bar_gen   = 0;

// ---------------------------------------------------------------------------
// Software grid barrier (all NBLK blocks resident)
// ---------------------------------------------------------------------------
__device__ __forceinline__ void grid_barrier() {
    __threadfence();
    __syncthreads();
    if (threadIdx.x == 0) {
        unsigned gen = *(volatile unsigned*)&g_bar_gen;
        unsigned old = atomicAdd(&g_bar_count, 1u);
        if (old == NBLK - 1) {
            g_bar_count = 0;
            __threadfence();
            atomicAdd(&g_bar_gen, 1u);
        } else {
            while (*(volatile unsigned*)&g_bar_gen == gen) { }
        }
        __threadfence();
    }
    __syncthreads();
}

// ---------------------------------------------------------------------------
// cp.async helpers (sm_80-baseline PTX)
// ---------------------------------------------------------------------------
__device__ __forceinline__ uint32_t smem_u32(const void* p) {
    uint32_t a;
    asm("{ .reg .u64 t; cvta.to.shared.u64 t, %1; cvt.u32.u64 %0, t; }"
        : "=r"(a) : "l"(p));
    return a;
}
__device__ __forceinline__ void cp16(uint32_t dst, const void* src) {
    asm volatile("cp.async.cg.shared.global [%0], [%1], 16;"
                 :: "r"(dst), "l"(src));
}
__device__ __forceinline__ void cp_commit() {
    asm volatile("cp.async.commit_group;" ::: "memory");
}
template <int N>
__device__ __forceinline__ void cp_wait() {
    asm volatile("cp.async.wait_group %0;" :: "n"(N) : "memory");
}

// fp16 mma: D(16x8,f32) += A(16x16,f16,row) * B(16x8,f16,col)
__device__ __forceinline__ void mma16(float* c,
                                      unsigned a0, unsigned a1,
                                      unsigned a2, unsigned a3,
                                      unsigned b0, unsigned b1) {
    asm volatile(
        "mma.sync.aligned.m16n8k16.row.col.f32.f16.f16.f32 "
        "{%0,%1,%2,%3}, {%4,%5,%6,%7}, {%8,%9}, {%0,%1,%2,%3};"
        : "+f"(c[0]), "+f"(c[1]), "+f"(c[2]), "+f"(c[3])
        : "r"(a0), "r"(a1), "r"(a2), "r"(a3), "r"(b0), "r"(b1));
}

__device__ __forceinline__ unsigned pack_h2(float x, float y) {
    __half2 h = __floats2half2_rn(x, y);
    return *reinterpret_cast<unsigned*>(&h);
}

// ===========================================================================
// WMMA tf32 input GEMM (unchanged — passing):
//   gates[m, n] = bias[n] + sum_k A[m,k] * W[n,k]      (C = A · Wᵀ)
// ===========================================================================
#define BM 128
#define BN 128
#define BK 16
#define APITCH 20
#define STG_FLOATS (BM * APITCH)
#define CPITCH 68
#define GEMM_SM_FLOATS (4 * STG_FLOATS + 128)

template <bool LAYER0>
__device__ __forceinline__ void load_stage(float* As, float* Ws, int s, int c,
                                           const float* __restrict__ A,
                                           const float* __restrict__ W,
                                           int m0, int n0, int tid)
{
    const int k0 = c * BK;
    float* as = As + s * STG_FLOATS;
    float* ws = Ws + s * STG_FLOATS;
#pragma unroll
    for (int i = 0; i < 2; i++) {
        int idx = tid + i * 256;
        int row = idx >> 2, seg = idx & 3;
        const float* src;
        if (LAYER0) {
            int m = m0 + row;
            src = A + ((size_t)(m & 63) * T_ + (m >> 6)) * D_ + k0 + seg * 4;
        } else {
            src = A + (size_t)(m0 + row) * H_ + k0 + seg * 4;
        }
        cp16(smem_u32(&as[row * APITCH + seg * 4]), src);
    }
#pragma unroll
    for (int i = 0; i < 2; i++) {
        int idx = tid + i * 256;
        int row = idx >> 2, seg = idx & 3;
        cp16(smem_u32(&ws[row * APITCH + seg * 4]),
             W + (size_t)(n0 + row) * H_ + k0 + seg * 4);
    }
    cp_commit();
}

template <bool LAYER0>
__global__ void __launch_bounds__(256)
gemm_gates_tc(const float* __restrict__ x,
              const float* __restrict__ Wih_all,
              const float* __restrict__ bih_all,
              const float* __restrict__ bhh_all,
              int layer, int in_sel)
{
    __shared__ float sm[GEMM_SM_FLOATS];
    float* As    = sm;
    float* Ws    = sm + 2 * STG_FLOATS;
    float* biasS = sm + 4 * STG_FLOATS;
    float* Cbuf  = sm;

    const float* A = LAYER0 ? x : (in_sel == 0 ? g_seq0 : g_seq1);
    const float* W = Wih_all + (size_t)layer * G_ * H_;

    const int tid = threadIdx.x;
    const int n0  = blockIdx.x * BN;
    const int m0  = blockIdx.y * BM;
    const int wid = tid >> 5;
    const int wm  = wid & 3;
    const int wn  = wid >> 2;

    if (tid < 128)
        biasS[tid] = bih_all[(size_t)layer * G_ + n0 + tid]
                   + bhh_all[(size_t)layer * G_ + n0 + tid];

    wmma::fragment<wmma::accumulator, 16, 16, 8, float> cf[2][4];
#pragma unroll
    for (int i = 0; i < 2; i++)
#pragma unroll
        for (int j = 0; j < 4; j++) wmma::fill_fragment(cf[i][j], 0.0f);

    load_stage<LAYER0>(As, Ws, 0, 0, A, W, m0, n0, tid);

    const int NC = H_ / BK;
    for (int c = 0; c < NC; c++) {
        const int s = c & 1;
        if (c + 1 < NC) {
            load_stage<LAYER0>(As, Ws, s ^ 1, c + 1, A, W, m0, n0, tid);
            cp_wait<1>();
        } else {
            cp_wait<0>();
        }
        __syncthreads();

        const float* as = As + s * STG_FLOATS;
        const float* ws = Ws + s * STG_FLOATS;
#pragma unroll
        for (int kk = 0; kk < BK; kk += 8) {
            wmma::fragment<wmma::matrix_a, 16, 16, 8, wmma::precision::tf32,
                           wmma::row_major> af[2];
            wmma::fragment<wmma::matrix_b, 16, 16, 8, wmma::precision::tf32,
                           wmma::col_major> bf[4];
#pragma unroll
            for (int i = 0; i < 2; i++) {
                wmma::load_matrix_sync(af[i],
                    as + (wm * 32 + i * 16) * APITCH + kk, APITCH);
#pragma unroll
                for (int e = 0; e < af[i].num_elements; e++)
                    af[i].x[e] = wmma::__float_to_tf32(af[i].x[e]);
            }
#pragma unroll
            for (int j = 0; j < 4; j++) {
                wmma::load_matrix_sync(bf[j],
                    ws + (wn * 64 + j * 16) * APITCH + kk, APITCH);
#pragma unroll
                for (int e = 0; e < bf[j].num_elements; e++)
                    bf[j].x[e] = wmma::__float_to_tf32(bf[j].x[e]);
            }
#pragma unroll
            for (int i = 0; i < 2; i++)
#pragma unroll
                for (int j = 0; j < 4; j++)
                    wmma::mma_sync(cf[i][j], af[i], bf[j], cf[i][j]);
        }
        __syncthreads();
    }

#pragma unroll
    for (int half = 0; half < 2; half++) {
        if (wn == half) {
#pragma unroll
            for (int i = 0; i < 2; i++)
#pragma unroll
                for (int j = 0; j < 4; j++)
                    wmma::store_matrix_sync(
                        &Cbuf[(wm * 32 + i * 16) * CPITCH + j * 16],
                        cf[i][j], CPITCH, wmma::mem_row_major);
        }
        __syncthreads();
#pragma unroll
        for (int q = 0; q < 8; q++) {
            int lin = q * 256 + tid;
            int row = lin >> 4;
            int c4  = lin & 15;
            float4 v = *reinterpret_cast<const float4*>(&Cbuf[row * CPITCH + c4 * 4]);
            int n = half * 64 + c4 * 4;
            v.x += biasS[n + 0];
            v.y += biasS[n + 1];
            v.z += biasS[n + 2];
            v.w += biasS[n + 3];
            *reinterpret_cast<float4*>(
                &g_gates[(size_t)(m0 + row) * G_ + n0 + n]) = v;
        }
        __syncthreads();
    }
}

// ===========================================================================
// Persistent recurrent kernel v5: fp16 m16n8k16 (same 10-bit mantissa as
// tf32 => same precision), Whh fragments in registers (64 regs, half of
// tf32), h stored fp16 (half the LDG instructions & bytes).
// 8 warps = 8 K-eighths (128 k each); each warp covers all 64 batch rows
// (4 m-frags) and all 32 gate cols (4 n-frags). Mainloop: 16-load bursts
// (full MLP) + mma — NO shared memory, NO syncs inside the K loop.
// 8 K-split partials reduced through SMEM in the elementwise phase.
// ===========================================================================
#define PP 36                                  // pre pitch floats
#define PRE_FL (64 * PP)                       // 2304
#define NPART 8
#define PSMEM_BYTES (NPART * PRE_FL * 4)       // 73,728 B

__global__ void __launch_bounds__(NTHR, 1)
lstm_persist_tc(const float* __restrict__ Whh_all, int layer, int out_sel)
{
    extern __shared__ float preS[];            // [8][64][PP]

    const float* W      = Whh_all + (size_t)layer * G_ * H_;
    float*       seqout = (out_sel == 0) ? g_seq0 : g_seq1;

    const int jb   = blockIdx.x;
    const int tid  = threadIdx.x;
    const int lane = tid & 31;
    const int wid  = tid >> 5;       // K-eighth: k in [wid*128, wid*128+128)
    const int grp  = lane >> 2;      // 0..7
    const int tq   = lane & 3;       // 0..3

    const int eb  = tid >> 2;        // batch row for elementwise
    const int ejj = (tid & 3) * 2;
    const int jg0 = jb * 8 + ejj;

    // ---- Whh B-fragments -> registers (once per layer), fp16 ----
    // m16n8k16 col-major B: b0 = {W[n][k=2tq], W[n][2tq+1]},
    //                       b1 = {W[n][2tq+8], W[n][2tq+9]}, n = grp.
    unsigned bw[8][4][2];
    {
        const float* wbase = W + (size_t)(jb * 8 + grp) * H_ + wid * 128 + 2 * tq;
#pragma unroll
        for (int nt = 0; nt < 4; nt++) {
            const float* wr = wbase + (size_t)nt * H_ * H_;
#pragma unroll
            for (int k16 = 0; k16 < 8; k16++) {
                bw[k16][nt][0] = pack_h2(wr[k16 * 16],     wr[k16 * 16 + 1]);
                bw[k16][nt][1] = pack_h2(wr[k16 * 16 + 8], wr[k16 * 16 + 9]);
            }
        }
    }

    // ---- zero initial h (64K halves = 32K uints, 256 uints per block) ----
    reinterpret_cast<unsigned*>(g_hA)[jb * 256 + tid] = 0u;
    reinterpret_cast<unsigned*>(g_hB)[jb * 256 + tid] = 0u;

    float2 creg = make_float2(0.0f, 0.0f);

    grid_barrier();

    for (int t = 0; t < T_; t++) {
        const __half* hin  = (t & 1) ? g_hB : g_hA;
        __half*       hout = (t & 1) ? g_hA : g_hB;

        // input-gate contributions (latency hidden behind the K loop)
        const float* grow = g_gates + ((size_t)(t * B_ + eb)) * G_ + jg0;
        float2 G0 = *reinterpret_cast<const float2*>(grow);
        float2 G1 = *reinterpret_cast<const float2*>(grow + H_);
        float2 G2 = *reinterpret_cast<const float2*>(grow + 2 * H_);
        float2 G3 = *reinterpret_cast<const float2*>(grow + 3 * H_);

        float acc[4][4][4];              // [m-frag][gate][c-regs]
#pragma unroll
        for (int mf = 0; mf < 4; mf++)
#pragma unroll
            for (int nt = 0; nt < 4; nt++)
#pragma unroll
                for (int r = 0; r < 4; r++) acc[mf][nt][r] = 0.0f;

#pragma unroll
        for (int i = 0; i < 8; i++) {             // 8 k16 steps in my eighth
            const int kb = wid * 128 + i * 16;
            unsigned a[4][4];
            // 16-load burst: full MLP before any consumer
#pragma unroll
            for (int mf = 0; mf < 4; mf++) {
                const unsigned* p0 = reinterpret_cast<const unsigned*>(
                    hin + (mf * 16 + grp) * H_ + kb) + tq;
                const unsigned* p1 = p0 + 4 * H_;   // +8 rows (H_ halves = H_/2 uints per row)
                a[mf][0] = __ldcg(p0);
                a[mf][1] = __ldcg(p1);
                a[mf][2] = __ldcg(p0 + 4);
                a[mf][3] = __ldcg(p1 + 4);
            }
#pragma unroll
            for (int mf = 0; mf < 4; mf++)
#pragma unroll
                for (int nt = 0; nt < 4; nt++)
                    mma16(acc[mf][nt], a[mf][0], a[mf][1], a[mf][2], a[mf][3],
                          bw[i][nt][0], bw[i][nt][1]);
        }

        // stage my K-split partial
        {
            float* pr = preS + wid * PRE_FL;
#pragma unroll
            for (int mf = 0; mf < 4; mf++) {
                const int rm = mf * 16 + grp;
#pragma unroll
                for (int nt = 0; nt < 4; nt++) {
                    const int cn = nt * 8 + 2 * tq;
                    *reinterpret_cast<float2*>(&pr[rm * PP + cn]) =
                        make_float2(acc[mf][nt][0], acc[mf][nt][1]);
                    *reinterpret_cast<float2*>(&pr[(rm + 8) * PP + cn]) =
                        make_float2(acc[mf][nt][2], acc[mf][nt][3]);
                }
            }
        }
        __syncthreads();

        // elementwise: 2 cells per thread, summing the 8 K-split partials
        {
            float i0 = G0.x, i1 = G0.y, f0 = G1.x, f1 = G1.y;
            float g0 = G2.x, g1 = G2.y, o0 = G3.x, o1 = G3.y;
#pragma unroll
            for (int p = 0; p < NPART; p++) {
                const float* pr = preS + p * PRE_FL + eb * PP;
                float2 v;
                v = *reinterpret_cast<const float2*>(&pr[ejj]);
                i0 += v.x; i1 += v.y;
                v = *reinterpret_cast<const float2*>(&pr[8 + ejj]);
                f0 += v.x; f1 += v.y;
                v = *reinterpret_cast<const float2*>(&pr[16 + ejj]);
                g0 += v.x; g1 += v.y;
                v = *reinterpret_cast<const float2*>(&pr[24 + ejj]);
                o0 += v.x; o1 += v.y;
            }
            i0 = 1.0f / (1.0f + __expf(-i0));
            i1 = 1.0f / (1.0f + __expf(-i1));
            f0 = 1.0f / (1.0f + __expf(-f0));
            f1 = 1.0f / (1.0f + __expf(-f1));
            o0 = 1.0f / (1.0f + __expf(-o0));
            o1 = 1.0f / (1.0f + __expf(-o1));
            g0 = tanhf(g0);
            g1 = tanhf(g1);
            creg.x = f0 * creg.x + i0 * g0;
            creg.y = f1 * creg.y + i1 * g1;
            float hx = o0 * tanhf(creg.x);
            float hy = o1 * tanhf(creg.y);
            // ping-pong h: fp16 (next step's MMA A operand)
            *reinterpret_cast<unsigned*>(&hout[eb * H_ + jg0]) = pack_h2(hx, hy);
            // sequence output: full precision (next layer's input GEMM)
            *reinterpret_cast<float2*>(&seqout[(size_t)(t * B_ + eb) * H_ + jg0]) =
                make_float2(hx, hy);
        }

        grid_barrier();   // entry __syncthreads also protects preS reuse
    }
}

// ---------------------------------------------------------------------------
// Final FC: reads the FULL-PRECISION final h from the layer-3 sequence
// buffer (g_seq1, t = 511) — the fp16 ping-pong never touches the output.
// ---------------------------------------------------------------------------
__global__ void __launch_bounds__(256)
fc_kernel(const float* __restrict__ fc_w, const float* __restrict__ fc_b,
          float* __restrict__ out)
{
    int b = blockIdx.x;
    int o = threadIdx.x;
    const float4* hv = reinterpret_cast<const float4*>(
        &g_seq1[(size_t)((T_ - 1) * B_ + b) * H_]);
    const float4* wv = reinterpret_cast<const float4*>(&fc_w[(size_t)o * H_]);
    float s = 0.0f;
#pragma unroll 8
    for (int k = 0; k < H_ / 4; k++) {
        float4 a = hv[k];
        float4 w = wv[k];
        s += a.x * w.x + a.y * w.y + a.z * w.z + a.w * w.w;
    }
    out[b * O_ + o] = s + fc_b[o];
}

// ---------------------------------------------------------------------------
// Launch: 9 graph nodes (4 wmma-GEMM + 4 persistent-TC + 1 FC)
// ---------------------------------------------------------------------------
extern "C" void kernel_launch(void* const* d_in, const int* in_sizes, int n_in,
                              void* d_out, int out_size)
{
    (void)in_sizes; (void)n_in; (void)out_size;
    const float* x    = (const float*)d_in[0];
    const float* Wih  = (const float*)d_in[1];
    const float* Whh  = (const float*)d_in[2];
    const float* bih  = (const float*)d_in[3];
    const float* bhh  = (const float*)d_in[4];
    const float* fc_w = (const float*)d_in[5];
    const float* fc_b = (const float*)d_in[6];
    float* out = (float*)d_out;

    cudaFuncSetAttribute(lstm_persist_tc,
                         cudaFuncAttributeMaxDynamicSharedMemorySize, PSMEM_BYTES);

    const dim3 ggrid(G_ / BN, TB_ / BM);   // (32, 256)
    const int in_sel[L_]  = { 0, 0, 1, 0 };
    const int out_sel[L_] = { 0, 1, 0, 1 };

    for (int l = 0; l < L_; l++) {
        if (l == 0)
            gemm_gates_tc<true ><<<ggrid, 256>>>(x, Wih, bih, bhh, l, 0);
        else
            gemm_gates_tc<false><<<ggrid, 256>>>(nullptr, Wih, bih, bhh, l, in_sel[l]);
        lstm_persist_tc<<<NBLK, NTHR, PSMEM_BYTES>>>(Whh, l, out_sel[l]);
    }
    fc_kernel<<<B_, 256>>>(fc_w, fc_b, out);
}

// round 12
// speedup vs baseline: 3.8400x; 1.5114x over previous
#include <cuda_runtime.h>
#include <cuda_fp16.h>
#include <math.h>
#include <stddef.h>
#include <stdint.h>
#include <mma.h>

using namespace nvcuda;

// Problem dims (fixed)
#define B_   64
#define T_   512
#define D_   1024
#define H_   1024
#define L_   4
#define G_   4096           // 4*H
#define O_   256
#define TB_  (T_ * B_)      // 32768

#define NBLK 128            // persistent-kernel grid
#define NTHR 256

// ---------------------------------------------------------------------------
// Device scratch (static globals — no allocation allowed)
// ---------------------------------------------------------------------------
__device__ float  g_gates[(size_t)TB_ * G_];  // 512 MB: input-part of gates
__device__ __half g_xh  [(size_t)TB_ * D_];   // 64 MB: x, fp16, [t*B+b][D]
__device__ __half g_wh  [(size_t)G_ * H_];    // 8 MB: current layer Wih fp16
__device__ __half g_seqh0[(size_t)TB_ * H_];  // 64 MB: seq ping (fp16)
__device__ __half g_seqh1[(size_t)TB_ * H_];  // 64 MB: seq pong (fp16)
__device__ __half g_hA[B_ * H_];              // fp16 h ping
__device__ __half g_hB[B_ * H_];              // fp16 h pong

__device__ unsigned g_bar_count = 0;
__device__ unsigned g_bar_gen   = 0;

// ---------------------------------------------------------------------------
// Software grid barrier (all NBLK blocks resident)
// ---------------------------------------------------------------------------
__device__ __forceinline__ void grid_barrier() {
    __threadfence();
    __syncthreads();
    if (threadIdx.x == 0) {
        unsigned gen = *(volatile unsigned*)&g_bar_gen;
        unsigned old = atomicAdd(&g_bar_count, 1u);
        if (old == NBLK - 1) {
            g_bar_count = 0;
            __threadfence();
            atomicAdd(&g_bar_gen, 1u);
        } else {
            while (*(volatile unsigned*)&g_bar_gen == gen) { }
        }
        __threadfence();
    }
    __syncthreads();
}

// ---------------------------------------------------------------------------
// cp.async helpers
// ---------------------------------------------------------------------------
__device__ __forceinline__ uint32_t smem_u32(const void* p) {
    uint32_t a;
    asm("{ .reg .u64 t; cvta.to.shared.u64 t, %1; cvt.u32.u64 %0, t; }"
        : "=r"(a) : "l"(p));
    return a;
}
__device__ __forceinline__ void cp16(uint32_t dst, const void* src) {
    asm volatile("cp.async.cg.shared.global [%0], [%1], 16;"
                 :: "r"(dst), "l"(src));
}
__device__ __forceinline__ void cp_commit() {
    asm volatile("cp.async.commit_group;" ::: "memory");
}
template <int N>
__device__ __forceinline__ void cp_wait() {
    asm volatile("cp.async.wait_group %0;" :: "n"(N) : "memory");
}

// fp16 mma: D(16x8,f32) += A(16x16,f16,row) * B(16x8,f16,col)
__device__ __forceinline__ void mma16(float* c,
                                      unsigned a0, unsigned a1,
                                      unsigned a2, unsigned a3,
                                      unsigned b0, unsigned b1) {
    asm volatile(
        "mma.sync.aligned.m16n8k16.row.col.f32.f16.f16.f32 "
        "{%0,%1,%2,%3}, {%4,%5,%6,%7}, {%8,%9}, {%0,%1,%2,%3};"
        : "+f"(c[0]), "+f"(c[1]), "+f"(c[2]), "+f"(c[3])
        : "r"(a0), "r"(a1), "r"(a2), "r"(a3), "r"(b0), "r"(b1));
}

__device__ __forceinline__ unsigned pack_h2(float x, float y) {
    __half2 h = __floats2half2_rn(x, y);
    return *reinterpret_cast<unsigned*>(&h);
}

// ---------------------------------------------------------------------------
// One-time converts
// ---------------------------------------------------------------------------
// x [B,T,D] fp32 -> g_xh [t*B+b][D] fp16 (transpose folded in)
__global__ void __launch_bounds__(256)
conv_x(const float* __restrict__ x)
{
    const int m = blockIdx.x;              // t*B + b
    const int t = m >> 6, b = m & 63;
    const float4* src = reinterpret_cast<const float4*>(
        x + ((size_t)b * T_ + t) * D_);
    __half2* dst = reinterpret_cast<__half2*>(g_xh + (size_t)m * D_);
    for (int i = threadIdx.x; i < D_ / 4; i += 256) {
        float4 v = src[i];
        dst[2 * i]     = __floats2half2_rn(v.x, v.y);
        dst[2 * i + 1] = __floats2half2_rn(v.z, v.w);
    }
}

// Wih[layer] fp32 -> g_wh fp16
__global__ void __launch_bounds__(256)
conv_w(const float* __restrict__ Wih_all, int layer)
{
    const int r = blockIdx.x;              // 0..4095
    const float4* src = reinterpret_cast<const float4*>(
        Wih_all + ((size_t)layer * G_ + r) * H_);
    __half2* dst = reinterpret_cast<__half2*>(g_wh + (size_t)r * H_);
    for (int i = threadIdx.x; i < H_ / 4; i += 256) {
        float4 v = src[i];
        dst[2 * i]     = __floats2half2_rn(v.x, v.y);
        dst[2 * i + 1] = __floats2half2_rn(v.z, v.w);
    }
}

// ===========================================================================
// fp16 input GEMM:  gates[m, n] = bias[n] + sum_k A[m,k] * W[n,k]
//   A = g_xh (layer 0) or g_seqh (layers 1-3), W = g_wh. All [row][k] fp16.
// Tile BM=128 x BN=128, BK=32, 256 threads, wmma m16n16k16.
// ===========================================================================
#define BM 128
#define BN 128
#define BKH 32
#define APH 40                              // halves pitch (80 B, 16B mult)
#define STGH (BM * APH)                     // 5120 halves per stage/matrix
#define CPITCH 68
#define GEMM_SM_BYTES (4 * STGH * 2 + 512)  // 40960 data + 512 bias

__device__ __forceinline__ void load_stage_h(__half* smh, int s, int c,
                                             const __half* __restrict__ A,
                                             const __half* __restrict__ W,
                                             int m0, int n0, int tid)
{
    const int k0 = c * BKH;
    __half* as = smh + s * STGH;
    __half* ws = smh + 2 * STGH + s * STGH;
#pragma unroll
    for (int i = 0; i < 2; i++) {           // A: 128 rows x 4 segs of 8 halves
        int idx = tid + i * 256;
        int row = idx >> 2, seg = idx & 3;
        cp16(smem_u32(&as[row * APH + seg * 8]),
             A + (size_t)(m0 + row) * H_ + k0 + seg * 8);
    }
#pragma unroll
    for (int i = 0; i < 2; i++) {           // W
        int idx = tid + i * 256;
        int row = idx >> 2, seg = idx & 3;
        cp16(smem_u32(&ws[row * APH + seg * 8]),
             W + (size_t)(n0 + row) * H_ + k0 + seg * 8);
    }
    cp_commit();
}

__global__ void __launch_bounds__(256)
gemm_gates_h(const __half* __restrict__ A,
             const float* __restrict__ bih_all,
             const float* __restrict__ bhh_all,
             int layer)
{
    __shared__ __align__(16) char smraw[GEMM_SM_BYTES];
    __half* smh   = reinterpret_cast<__half*>(smraw);
    float*  biasS = reinterpret_cast<float*>(smraw + 4 * STGH * 2);
    float*  Cbuf  = reinterpret_cast<float*>(smraw);   // epilogue overlay

    const __half* W = g_wh;

    const int tid = threadIdx.x;
    const int n0  = blockIdx.x * BN;
    const int m0  = blockIdx.y * BM;
    const int wid = tid >> 5;
    const int wm  = wid & 3;                // m-tile (32 rows)
    const int wn  = wid >> 2;               // n-half (64 cols)

    if (tid < 128)
        biasS[tid] = bih_all[(size_t)layer * G_ + n0 + tid]
                   + bhh_all[(size_t)layer * G_ + n0 + tid];

    wmma::fragment<wmma::accumulator, 16, 16, 16, float> cf[2][4];
#pragma unroll
    for (int i = 0; i < 2; i++)
#pragma unroll
        for (int j = 0; j < 4; j++) wmma::fill_fragment(cf[i][j], 0.0f);

    load_stage_h(smh, 0, 0, A, W, m0, n0, tid);

    const int NC = H_ / BKH;                // 32
    for (int c = 0; c < NC; c++) {
        const int s = c & 1;
        if (c + 1 < NC) {
            load_stage_h(smh, s ^ 1, c + 1, A, W, m0, n0, tid);
            cp_wait<1>();
        } else {
            cp_wait<0>();
        }
        __syncthreads();

        const __half* as = smh + s * STGH;
        const __half* ws = smh + 2 * STGH + s * STGH;
#pragma unroll
        for (int kk = 0; kk < BKH; kk += 16) {
            wmma::fragment<wmma::matrix_a, 16, 16, 16, __half,
                           wmma::row_major> af[2];
            wmma::fragment<wmma::matrix_b, 16, 16, 16, __half,
                           wmma::col_major> bf[4];
#pragma unroll
            for (int i = 0; i < 2; i++)
                wmma::load_matrix_sync(af[i],
                    as + (wm * 32 + i * 16) * APH + kk, APH);
#pragma unroll
            for (int j = 0; j < 4; j++)
                wmma::load_matrix_sync(bf[j],
                    ws + (wn * 64 + j * 16) * APH + kk, APH);
#pragma unroll
            for (int i = 0; i < 2; i++)
#pragma unroll
                for (int j = 0; j < 4; j++)
                    wmma::mma_sync(cf[i][j], af[i], bf[j], cf[i][j]);
        }
        __syncthreads();
    }

    // Epilogue: two n-halves staged through SMEM, bias fused, float4 stores
#pragma unroll
    for (int half = 0; half < 2; half++) {
        if (wn == half) {
#pragma unroll
            for (int i = 0; i < 2; i++)
#pragma unroll
                for (int j = 0; j < 4; j++)
                    wmma::store_matrix_sync(
                        &Cbuf[(wm * 32 + i * 16) * CPITCH + j * 16],
                        cf[i][j], CPITCH, wmma::mem_row_major);
        }
        __syncthreads();
#pragma unroll
        for (int q = 0; q < 8; q++) {
            int lin = q * 256 + tid;
            int row = lin >> 4;
            int c4  = lin & 15;
            float4 v = *reinterpret_cast<const float4*>(&Cbuf[row * CPITCH + c4 * 4]);
            int n = half * 64 + c4 * 4;
            v.x += biasS[n + 0];
            v.y += biasS[n + 1];
            v.z += biasS[n + 2];
            v.w += biasS[n + 3];
            *reinterpret_cast<float4*>(
                &g_gates[(size_t)(m0 + row) * G_ + n0 + n]) = v;
        }
        __syncthreads();
    }
}

// ===========================================================================
// Persistent recurrent kernel (R11 design, unchanged except fp16 seq out).
// 8 warps = 8 K-eighths; Whh fp16 fragments in registers; h fp16 ping-pong;
// mainloop = 16-load __ldcg bursts + mma16; NO smem/syncs in the K loop.
// ===========================================================================
#define PP 36
#define PRE_FL (64 * PP)
#define NPART 8
#define PSMEM_BYTES (NPART * PRE_FL * 4)       // 73,728 B

__global__ void __launch_bounds__(NTHR, 1)
lstm_persist_tc(const float* __restrict__ Whh_all, int layer, int out_sel)
{
    extern __shared__ float preS[];            // [8][64][PP]

    const float* W      = Whh_all + (size_t)layer * G_ * H_;
    __half*      seqout = (out_sel == 0) ? g_seqh0 : g_seqh1;

    const int jb   = blockIdx.x;
    const int tid  = threadIdx.x;
    const int lane = tid & 31;
    const int wid  = tid >> 5;       // K-eighth
    const int grp  = lane >> 2;      // 0..7
    const int tq   = lane & 3;       // 0..3

    const int eb  = tid >> 2;        // batch row for elementwise
    const int ejj = (tid & 3) * 2;
    const int jg0 = jb * 8 + ejj;

    // Whh B-fragments -> registers (fp16)
    unsigned bw[8][4][2];
    {
        const float* wbase = W + (size_t)(jb * 8 + grp) * H_ + wid * 128 + 2 * tq;
#pragma unroll
        for (int nt = 0; nt < 4; nt++) {
            const float* wr = wbase + (size_t)nt * H_ * H_;
#pragma unroll
            for (int k16 = 0; k16 < 8; k16++) {
                bw[k16][nt][0] = pack_h2(wr[k16 * 16],     wr[k16 * 16 + 1]);
                bw[k16][nt][1] = pack_h2(wr[k16 * 16 + 8], wr[k16 * 16 + 9]);
            }
        }
    }

    // zero initial h
    reinterpret_cast<unsigned*>(g_hA)[jb * 256 + tid] = 0u;
    reinterpret_cast<unsigned*>(g_hB)[jb * 256 + tid] = 0u;

    float2 creg = make_float2(0.0f, 0.0f);

    grid_barrier();

    for (int t = 0; t < T_; t++) {
        const __half* hin  = (t & 1) ? g_hB : g_hA;
        __half*       hout = (t & 1) ? g_hA : g_hB;

        const float* grow = g_gates + ((size_t)(t * B_ + eb)) * G_ + jg0;
        float2 G0 = *reinterpret_cast<const float2*>(grow);
        float2 G1 = *reinterpret_cast<const float2*>(grow + H_);
        float2 G2 = *reinterpret_cast<const float2*>(grow + 2 * H_);
        float2 G3 = *reinterpret_cast<const float2*>(grow + 3 * H_);

        float acc[4][4][4];
#pragma unroll
        for (int mf = 0; mf < 4; mf++)
#pragma unroll
            for (int nt = 0; nt < 4; nt++)
#pragma unroll
                for (int r = 0; r < 4; r++) acc[mf][nt][r] = 0.0f;

#pragma unroll
        for (int i = 0; i < 8; i++) {
            const int kb = wid * 128 + i * 16;
            unsigned a[4][4];
#pragma unroll
            for (int mf = 0; mf < 4; mf++) {
                const unsigned* p0 = reinterpret_cast<const unsigned*>(
                    hin + (mf * 16 + grp) * H_ + kb) + tq;
                const unsigned* p1 = p0 + 4 * H_;
                a[mf][0] = __ldcg(p0);
                a[mf][1] = __ldcg(p1);
                a[mf][2] = __ldcg(p0 + 4);
                a[mf][3] = __ldcg(p1 + 4);
            }
#pragma unroll
            for (int mf = 0; mf < 4; mf++)
#pragma unroll
                for (int nt = 0; nt < 4; nt++)
                    mma16(acc[mf][nt], a[mf][0], a[mf][1], a[mf][2], a[mf][3],
                          bw[i][nt][0], bw[i][nt][1]);
        }

        // stage my K-split partial
        {
            float* pr = preS + wid * PRE_FL;
#pragma unroll
            for (int mf = 0; mf < 4; mf++) {
                const int rm = mf * 16 + grp;
#pragma unroll
                for (int nt = 0; nt < 4; nt++) {
                    const int cn = nt * 8 + 2 * tq;
                    *reinterpret_cast<float2*>(&pr[rm * PP + cn]) =
                        make_float2(acc[mf][nt][0], acc[mf][nt][1]);
                    *reinterpret_cast<float2*>(&pr[(rm + 8) * PP + cn]) =
                        make_float2(acc[mf][nt][2], acc[mf][nt][3]);
                }
            }
        }
        __syncthreads();

        // elementwise: 2 cells per thread, summing the 8 K-split partials
        {
            float i0 = G0.x, i1 = G0.y, f0 = G1.x, f1 = G1.y;
            float g0 = G2.x, g1 = G2.y, o0 = G3.x, o1 = G3.y;
#pragma unroll
            for (int p = 0; p < NPART; p++) {
                const float* pr = preS + p * PRE_FL + eb * PP;
                float2 v;
                v = *reinterpret_cast<const float2*>(&pr[ejj]);
                i0 += v.x; i1 += v.y;
                v = *reinterpret_cast<const float2*>(&pr[8 + ejj]);
                f0 += v.x; f1 += v.y;
                v = *reinterpret_cast<const float2*>(&pr[16 + ejj]);
                g0 += v.x; g1 += v.y;
                v = *reinterpret_cast<const float2*>(&pr[24 + ejj]);
                o0 += v.x; o1 += v.y;
            }
            i0 = 1.0f / (1.0f + __expf(-i0));
            i1 = 1.0f / (1.0f + __expf(-i1));
            f0 = 1.0f / (1.0f + __expf(-f0));
            f1 = 1.0f / (1.0f + __expf(-f1));
            o0 = 1.0f / (1.0f + __expf(-o0));
            o1 = 1.0f / (1.0f + __expf(-o1));
            g0 = tanhf(g0);
            g1 = tanhf(g1);
            creg.x = f0 * creg.x + i0 * g0;
            creg.y = f1 * creg.y + i1 * g1;
            float hx = o0 * tanhf(creg.x);
            float hy = o1 * tanhf(creg.y);
            unsigned hp = pack_h2(hx, hy);
            // ping-pong h (next step's MMA A operand)
            *reinterpret_cast<unsigned*>(&hout[eb * H_ + jg0]) = hp;
            // sequence output fp16 (next layer's GEMM A / final FC)
            *reinterpret_cast<unsigned*>(
                &seqout[(size_t)(t * B_ + eb) * H_ + jg0]) = hp;
        }

        grid_barrier();
    }
}

// ---------------------------------------------------------------------------
// Final FC: reads fp16 final h (layer 3 seq = g_seqh1, t = 511), fp32 accum.
// ---------------------------------------------------------------------------
__global__ void __launch_bounds__(256)
fc_kernel(const float* __restrict__ fc_w, const float* __restrict__ fc_b,
          float* __restrict__ out)
{
    int b = blockIdx.x;
    int o = threadIdx.x;
    const __half2* hv = reinterpret_cast<const __half2*>(
        &g_seqh1[(size_t)((T_ - 1) * B_ + b) * H_]);
    const float2* wv = reinterpret_cast<const float2*>(&fc_w[(size_t)o * H_]);
    float s = 0.0f;
#pragma unroll 8
    for (int k = 0; k < H_ / 2; k++) {
        float2 a = __half22float2(hv[k]);
        float2 w = wv[k];
        s += a.x * w.x + a.y * w.y;
    }
    out[b * O_ + o] = s + fc_b[o];
}

// ---------------------------------------------------------------------------
// Launch: 14 graph nodes (1 conv_x + 4 conv_w + 4 GEMM + 4 persist + 1 FC)
// ---------------------------------------------------------------------------
extern "C" void kernel_launch(void* const* d_in, const int* in_sizes, int n_in,
                              void* d_out, int out_size)
{
    (void)in_sizes; (void)n_in; (void)out_size;
    const float* x    = (const float*)d_in[0];
    const float* Wih  = (const float*)d_in[1];
    const float* Whh  = (const float*)d_in[2];
    const float* bih  = (const float*)d_in[3];
    const float* bhh  = (const float*)d_in[4];
    const float* fc_w = (const float*)d_in[5];
    const float* fc_b = (const float*)d_in[6];
    float* out = (float*)d_out;

    cudaFuncSetAttribute(lstm_persist_tc,
                         cudaFuncAttributeMaxDynamicSharedMemorySize, PSMEM_BYTES);

    conv_x<<<TB_, 256>>>(x);

    const dim3 ggrid(G_ / BN, TB_ / BM);   // (32, 256)
    const int out_sel[L_] = { 0, 1, 0, 1 };
    // layer l input (fp16): l0 = g_xh; l>=1 = seq written by layer l-1
    __half* seq_in[L_];

    for (int l = 0; l < L_; l++) {
        conv_w<<<G_, 256>>>(Wih, l);
        const __half* A;
        if (l == 0) {
            // device-symbol addresses aren't host pointers; pass via kernel arg
            A = nullptr;  // resolved inside via flag
        }
        // Resolve A host-side using cudaGetSymbolAddress-free trick:
        // we instead dispatch three variants by pointer selection below.
        (void)A;
        // (actual dispatch below)
        void* a_ptr = nullptr;
        if (l == 0) {
            cudaGetSymbolAddress(&a_ptr, g_xh);
        } else if (out_sel[l - 1] == 0) {
            cudaGetSymbolAddress(&a_ptr, g_seqh0);
        } else {
            cudaGetSymbolAddress(&a_ptr, g_seqh1);
        }
        gemm_gates_h<<<ggrid, 256>>>((const __half*)a_ptr, bih, bhh, l);
        lstm_persist_tc<<<NBLK, NTHR, PSMEM_BYTES>>>(Whh, l, out_sel[l]);
        seq_in[l] = nullptr; (void)seq_in;
    }
    fc_kernel<<<B_, 256>>>(fc_w, fc_b, out);
}

// round 13
// speedup vs baseline: 4.1910x; 1.0914x over previous
#include <cuda_runtime.h>
#include <cuda_fp16.h>
#include <math.h>
#include <stddef.h>
#include <stdint.h>
#include <mma.h>

using namespace nvcuda;

// Problem dims (fixed)
#define B_   64
#define T_   512
#define D_   1024
#define H_   1024
#define L_   4
#define G_   4096           // 4*H
#define O_   256
#define TB_  (T_ * B_)      // 32768

#define NBLK 128            // persistent-kernel grid
#define NTHR 256

// ---------------------------------------------------------------------------
// Device scratch (static globals — no allocation allowed)
// ---------------------------------------------------------------------------
__device__ float  g_gates[(size_t)TB_ * G_];  // 512 MB: input-part of gates
__device__ __half g_xh  [(size_t)TB_ * D_];   // 64 MB: x, fp16, [t*B+b][D]
__device__ __half g_wh  [(size_t)G_ * H_];    // 8 MB: current layer Wih fp16
__device__ __half g_seqh0[(size_t)TB_ * H_];  // 64 MB: seq ping (fp16)
__device__ __half g_seqh1[(size_t)TB_ * H_];  // 64 MB: seq pong (fp16)
__device__ __half g_hA[B_ * H_];              // fp16 h ping
__device__ __half g_hB[B_ * H_];              // fp16 h pong

__device__ unsigned g_bar_count = 0;
__device__ unsigned g_bar_gen   = 0;
__device__ int      g_flags[NBLK * 32];       // padded: one 128B line per block

// ---------------------------------------------------------------------------
// Atomic grid barrier (self-resetting; used ONCE per layer for init)
// ---------------------------------------------------------------------------
__device__ __forceinline__ void grid_barrier_atomic() {
    __threadfence();
    __syncthreads();
    if (threadIdx.x == 0) {
        unsigned gen = *(volatile unsigned*)&g_bar_gen;
        unsigned old = atomicAdd(&g_bar_count, 1u);
        if (old == NBLK - 1) {
            g_bar_count = 0;
            __threadfence();
            atomicAdd(&g_bar_gen, 1u);
        } else {
            while (*(volatile unsigned*)&g_bar_gen == gen) { }
        }
        __threadfence();
    }
    __syncthreads();
}

// ---------------------------------------------------------------------------
// Distributed flag barrier (per-step): no atomic serialization.
// Producer: all threads fence, sync, thread 0 release-stores flag[jb] = val.
// Consumers: threads 0..127 each poll ONE flag until >= val, then sync.
// ---------------------------------------------------------------------------
__device__ __forceinline__ void flag_barrier(int jb, int tid, int val) {
    __threadfence();
    __syncthreads();
    if (tid == 0)
        *((volatile int*)&g_flags[jb * 32]) = val;
    if (tid < NBLK) {
        volatile int* f = &g_flags[tid * 32];
        while (*f < val) { }
    }
    __syncthreads();
}

// ---------------------------------------------------------------------------
// cp.async helpers
// ---------------------------------------------------------------------------
__device__ __forceinline__ uint32_t smem_u32(const void* p) {
    uint32_t a;
    asm("{ .reg .u64 t; cvta.to.shared.u64 t, %1; cvt.u32.u64 %0, t; }"
        : "=r"(a) : "l"(p));
    return a;
}
__device__ __forceinline__ void cp16(uint32_t dst, const void* src) {
    asm volatile("cp.async.cg.shared.global [%0], [%1], 16;"
                 :: "r"(dst), "l"(src));
}
__device__ __forceinline__ void cp_commit() {
    asm volatile("cp.async.commit_group;" ::: "memory");
}
template <int N>
__device__ __forceinline__ void cp_wait() {
    asm volatile("cp.async.wait_group %0;" :: "n"(N) : "memory");
}

// fp16 mma: D(16x8,f32) += A(16x16,f16,row) * B(16x8,f16,col)
__device__ __forceinline__ void mma16(float* c,
                                      unsigned a0, unsigned a1,
                                      unsigned a2, unsigned a3,
                                      unsigned b0, unsigned b1) {
    asm volatile(
        "mma.sync.aligned.m16n8k16.row.col.f32.f16.f16.f32 "
        "{%0,%1,%2,%3}, {%4,%5,%6,%7}, {%8,%9}, {%0,%1,%2,%3};"
        : "+f"(c[0]), "+f"(c[1]), "+f"(c[2]), "+f"(c[3])
        : "r"(a0), "r"(a1), "r"(a2), "r"(a3), "r"(b0), "r"(b1));
}

__device__ __forceinline__ unsigned pack_h2(float x, float y) {
    __half2 h = __floats2half2_rn(x, y);
    return *reinterpret_cast<unsigned*>(&h);
}

// fast sigmoid / tanh (MUFU-based; abs err ~1e-6)
__device__ __forceinline__ float fsig(float x) {
    return __fdividef(1.0f, 1.0f + __expf(-x));
}
__device__ __forceinline__ float ftanh(float x) {
    return 1.0f - __fdividef(2.0f, __expf(2.0f * x) + 1.0f);
}

// ---------------------------------------------------------------------------
// One-time converts
// ---------------------------------------------------------------------------
__global__ void __launch_bounds__(256)
conv_x(const float* __restrict__ x)
{
    const int m = blockIdx.x;              // t*B + b
    const int t = m >> 6, b = m & 63;
    const float4* src = reinterpret_cast<const float4*>(
        x + ((size_t)b * T_ + t) * D_);
    __half2* dst = reinterpret_cast<__half2*>(g_xh + (size_t)m * D_);
    for (int i = threadIdx.x; i < D_ / 4; i += 256) {
        float4 v = src[i];
        dst[2 * i]     = __floats2half2_rn(v.x, v.y);
        dst[2 * i + 1] = __floats2half2_rn(v.z, v.w);
    }
}

__global__ void __launch_bounds__(256)
conv_w(const float* __restrict__ Wih_all, int layer)
{
    const int r = blockIdx.x;              // 0..4095
    const float4* src = reinterpret_cast<const float4*>(
        Wih_all + ((size_t)layer * G_ + r) * H_);
    __half2* dst = reinterpret_cast<__half2*>(g_wh + (size_t)r * H_);
    for (int i = threadIdx.x; i < H_ / 4; i += 256) {
        float4 v = src[i];
        dst[2 * i]     = __floats2half2_rn(v.x, v.y);
        dst[2 * i + 1] = __floats2half2_rn(v.z, v.w);
    }
}

// ===========================================================================
// fp16 input GEMM (unchanged from R12 — passing):
//   gates[m, n] = bias[n] + sum_k A[m,k] * W[n,k]
// ===========================================================================
#define BM 128
#define BN 128
#define BKH 32
#define APH 40
#define STGH (BM * APH)
#define CPITCH 68
#define GEMM_SM_BYTES (4 * STGH * 2 + 512)

__device__ __forceinline__ void load_stage_h(__half* smh, int s, int c,
                                             const __half* __restrict__ A,
                                             const __half* __restrict__ W,
                                             int m0, int n0, int tid)
{
    const int k0 = c * BKH;
    __half* as = smh + s * STGH;
    __half* ws = smh + 2 * STGH + s * STGH;
#pragma unroll
    for (int i = 0; i < 2; i++) {
        int idx = tid + i * 256;
        int row = idx >> 2, seg = idx & 3;
        cp16(smem_u32(&as[row * APH + seg * 8]),
             A + (size_t)(m0 + row) * H_ + k0 + seg * 8);
    }
#pragma unroll
    for (int i = 0; i < 2; i++) {
        int idx = tid + i * 256;
        int row = idx >> 2, seg = idx & 3;
        cp16(smem_u32(&ws[row * APH + seg * 8]),
             W + (size_t)(n0 + row) * H_ + k0 + seg * 8);
    }
    cp_commit();
}

__global__ void __launch_bounds__(256)
gemm_gates_h(const __half* __restrict__ A,
             const float* __restrict__ bih_all,
             const float* __restrict__ bhh_all,
             int layer)
{
    __shared__ __align__(16) char smraw[GEMM_SM_BYTES];
    __half* smh   = reinterpret_cast<__half*>(smraw);
    float*  biasS = reinterpret_cast<float*>(smraw + 4 * STGH * 2);
    float*  Cbuf  = reinterpret_cast<float*>(smraw);

    const __half* W = g_wh;

    const int tid = threadIdx.x;
    const int n0  = blockIdx.x * BN;
    const int m0  = blockIdx.y * BM;
    const int wid = tid >> 5;
    const int wm  = wid & 3;
    const int wn  = wid >> 2;

    if (tid < 128)
        biasS[tid] = bih_all[(size_t)layer * G_ + n0 + tid]
                   + bhh_all[(size_t)layer * G_ + n0 + tid];

    wmma::fragment<wmma::accumulator, 16, 16, 16, float> cf[2][4];
#pragma unroll
    for (int i = 0; i < 2; i++)
#pragma unroll
        for (int j = 0; j < 4; j++) wmma::fill_fragment(cf[i][j], 0.0f);

    load_stage_h(smh, 0, 0, A, W, m0, n0, tid);

    const int NC = H_ / BKH;
    for (int c = 0; c < NC; c++) {
        const int s = c & 1;
        if (c + 1 < NC) {
            load_stage_h(smh, s ^ 1, c + 1, A, W, m0, n0, tid);
            cp_wait<1>();
        } else {
            cp_wait<0>();
        }
        __syncthreads();

        const __half* as = smh + s * STGH;
        const __half* ws = smh + 2 * STGH + s * STGH;
#pragma unroll
        for (int kk = 0; kk < BKH; kk += 16) {
            wmma::fragment<wmma::matrix_a, 16, 16, 16, __half,
                           wmma::row_major> af[2];
            wmma::fragment<wmma::matrix_b, 16, 16, 16, __half,
                           wmma::col_major> bf[4];
#pragma unroll
            for (int i = 0; i < 2; i++)
                wmma::load_matrix_sync(af[i],
                    as + (wm * 32 + i * 16) * APH + kk, APH);
#pragma unroll
            for (int j = 0; j < 4; j++)
                wmma::load_matrix_sync(bf[j],
                    ws + (wn * 64 + j * 16) * APH + kk, APH);
#pragma unroll
            for (int i = 0; i < 2; i++)
#pragma unroll
                for (int j = 0; j < 4; j++)
                    wmma::mma_sync(cf[i][j], af[i], bf[j], cf[i][j]);
        }
        __syncthreads();
    }

#pragma unroll
    for (int half = 0; half < 2; half++) {
        if (wn == half) {
#pragma unroll
            for (int i = 0; i < 2; i++)
#pragma unroll
                for (int j = 0; j < 4; j++)
                    wmma::store_matrix_sync(
                        &Cbuf[(wm * 32 + i * 16) * CPITCH + j * 16],
                        cf[i][j], CPITCH, wmma::mem_row_major);
        }
        __syncthreads();
#pragma unroll
        for (int q = 0; q < 8; q++) {
            int lin = q * 256 + tid;
            int row = lin >> 4;
            int c4  = lin & 15;
            float4 v = *reinterpret_cast<const float4*>(&Cbuf[row * CPITCH + c4 * 4]);
            int n = half * 64 + c4 * 4;
            v.x += biasS[n + 0];
            v.y += biasS[n + 1];
            v.z += biasS[n + 2];
            v.w += biasS[n + 3];
            *reinterpret_cast<float4*>(
                &g_gates[(size_t)(m0 + row) * G_ + n0 + n]) = v;
        }
        __syncthreads();
    }
}

// ===========================================================================
// Persistent recurrent kernel v6:
//  - distributed flag barrier (no atomic serialization per step)
//  - 2-deep software-pipelined K loop (prefetch burst i+1 during mma i)
//  - fast MUFU-based sigmoid/tanh
// ===========================================================================
#define PP 36
#define PRE_FL (64 * PP)
#define NPART 8
#define PSMEM_BYTES (NPART * PRE_FL * 4)       // 73,728 B

__device__ __forceinline__ void load_burst(unsigned a[4][4],
                                           const __half* __restrict__ hin,
                                           int kb, int grp, int tq)
{
#pragma unroll
    for (int mf = 0; mf < 4; mf++) {
        const unsigned* p0 = reinterpret_cast<const unsigned*>(
            hin + (mf * 16 + grp) * H_ + kb) + tq;
        const unsigned* p1 = p0 + 4 * H_;
        a[mf][0] = __ldcg(p0);
        a[mf][1] = __ldcg(p1);
        a[mf][2] = __ldcg(p0 + 4);
        a[mf][3] = __ldcg(p1 + 4);
    }
}

__global__ void __launch_bounds__(NTHR, 1)
lstm_persist_tc(const float* __restrict__ Whh_all, int layer, int out_sel)
{
    extern __shared__ float preS[];            // [8][64][PP]

    const float* W      = Whh_all + (size_t)layer * G_ * H_;
    __half*      seqout = (out_sel == 0) ? g_seqh0 : g_seqh1;

    const int jb   = blockIdx.x;
    const int tid  = threadIdx.x;
    const int lane = tid & 31;
    const int wid  = tid >> 5;       // K-eighth
    const int grp  = lane >> 2;      // 0..7
    const int tq   = lane & 3;       // 0..3

    const int eb  = tid >> 2;
    const int ejj = (tid & 3) * 2;
    const int jg0 = jb * 8 + ejj;

    // Whh B-fragments -> registers (fp16)
    unsigned bw[8][4][2];
    {
        const float* wbase = W + (size_t)(jb * 8 + grp) * H_ + wid * 128 + 2 * tq;
#pragma unroll
        for (int nt = 0; nt < 4; nt++) {
            const float* wr = wbase + (size_t)nt * H_ * H_;
#pragma unroll
            for (int k16 = 0; k16 < 8; k16++) {
                bw[k16][nt][0] = pack_h2(wr[k16 * 16],     wr[k16 * 16 + 1]);
                bw[k16][nt][1] = pack_h2(wr[k16 * 16 + 8], wr[k16 * 16 + 9]);
            }
        }
    }

    // zero initial h + reset my flag (behind the self-resetting atomic barrier)
    reinterpret_cast<unsigned*>(g_hA)[jb * 256 + tid] = 0u;
    reinterpret_cast<unsigned*>(g_hB)[jb * 256 + tid] = 0u;
    if (tid == 0) g_flags[jb * 32] = 0;

    float2 creg = make_float2(0.0f, 0.0f);

    grid_barrier_atomic();

    for (int t = 0; t < T_; t++) {
        const __half* hin  = (t & 1) ? g_hB : g_hA;
        __half*       hout = (t & 1) ? g_hA : g_hB;

        const float* grow = g_gates + ((size_t)(t * B_ + eb)) * G_ + jg0;
        float2 G0 = *reinterpret_cast<const float2*>(grow);
        float2 G1 = *reinterpret_cast<const float2*>(grow + H_);
        float2 G2 = *reinterpret_cast<const float2*>(grow + 2 * H_);
        float2 G3 = *reinterpret_cast<const float2*>(grow + 3 * H_);

        float acc[4][4][4];
#pragma unroll
        for (int mf = 0; mf < 4; mf++)
#pragma unroll
            for (int nt = 0; nt < 4; nt++)
#pragma unroll
                for (int r = 0; r < 4; r++) acc[mf][nt][r] = 0.0f;

        // 2-deep pipelined K loop over my 8 k16 bursts
        unsigned a[2][4][4];
        load_burst(a[0], hin, wid * 128, grp, tq);
#pragma unroll
        for (int i = 0; i < 8; i++) {
            if (i < 7)
                load_burst(a[(i + 1) & 1], hin, wid * 128 + (i + 1) * 16, grp, tq);
            unsigned (*ai)[4] = a[i & 1];
#pragma unroll
            for (int mf = 0; mf < 4; mf++)
#pragma unroll
                for (int nt = 0; nt < 4; nt++)
                    mma16(acc[mf][nt], ai[mf][0], ai[mf][1], ai[mf][2], ai[mf][3],
                          bw[i][nt][0], bw[i][nt][1]);
        }

        // stage my K-split partial
        {
            float* pr = preS + wid * PRE_FL;
#pragma unroll
            for (int mf = 0; mf < 4; mf++) {
                const int rm = mf * 16 + grp;
#pragma unroll
                for (int nt = 0; nt < 4; nt++) {
                    const int cn = nt * 8 + 2 * tq;
                    *reinterpret_cast<float2*>(&pr[rm * PP + cn]) =
                        make_float2(acc[mf][nt][0], acc[mf][nt][1]);
                    *reinterpret_cast<float2*>(&pr[(rm + 8) * PP + cn]) =
                        make_float2(acc[mf][nt][2], acc[mf][nt][3]);
                }
            }
        }
        __syncthreads();

        // elementwise: 2 cells per thread, summing the 8 K-split partials
        {
            float i0 = G0.x, i1 = G0.y, f0 = G1.x, f1 = G1.y;
            float g0 = G2.x, g1 = G2.y, o0 = G3.x, o1 = G3.y;
#pragma unroll
            for (int p = 0; p < NPART; p++) {
                const float* pr = preS + p * PRE_FL + eb * PP;
                float2 v;
                v = *reinterpret_cast<const float2*>(&pr[ejj]);
                i0 += v.x; i1 += v.y;
                v = *reinterpret_cast<const float2*>(&pr[8 + ejj]);
                f0 += v.x; f1 += v.y;
                v = *reinterpret_cast<const float2*>(&pr[16 + ejj]);
                g0 += v.x; g1 += v.y;
                v = *reinterpret_cast<const float2*>(&pr[24 + ejj]);
                o0 += v.x; o1 += v.y;
            }
            i0 = fsig(i0); i1 = fsig(i1);
            f0 = fsig(f0); f1 = fsig(f1);
            o0 = fsig(o0); o1 = fsig(o1);
            g0 = ftanh(g0); g1 = ftanh(g1);
            creg.x = f0 * creg.x + i0 * g0;
            creg.y = f1 * creg.y + i1 * g1;
            float hx = o0 * ftanh(creg.x);
            float hy = o1 * ftanh(creg.y);
            unsigned hp = pack_h2(hx, hy);
            *reinterpret_cast<unsigned*>(&hout[eb * H_ + jg0]) = hp;
            *reinterpret_cast<unsigned*>(
                &seqout[(size_t)(t * B_ + eb) * H_ + jg0]) = hp;
        }

        flag_barrier(jb, tid, t + 1);
    }
}

// ---------------------------------------------------------------------------
// Final FC: reads fp16 final h (layer 3 seq = g_seqh1, t = 511), fp32 accum.
// ---------------------------------------------------------------------------
__global__ void __launch_bounds__(256)
fc_kernel(const float* __restrict__ fc_w, const float* __restrict__ fc_b,
          float* __restrict__ out)
{
    int b = blockIdx.x;
    int o = threadIdx.x;
    const __half2* hv = reinterpret_cast<const __half2*>(
        &g_seqh1[(size_t)((T_ - 1) * B_ + b) * H_]);
    const float2* wv = reinterpret_cast<const float2*>(&fc_w[(size_t)o * H_]);
    float s = 0.0f;
#pragma unroll 8
    for (int k = 0; k < H_ / 2; k++) {
        float2 a = __half22float2(hv[k]);
        float2 w = wv[k];
        s += a.x * w.x + a.y * w.y;
    }
    out[b * O_ + o] = s + fc_b[o];
}

// ---------------------------------------------------------------------------
// Launch: 14 graph nodes (1 conv_x + 4 conv_w + 4 GEMM + 4 persist + 1 FC)
// ---------------------------------------------------------------------------
extern "C" void kernel_launch(void* const* d_in, const int* in_sizes, int n_in,
                              void* d_out, int out_size)
{
    (void)in_sizes; (void)n_in; (void)out_size;
    const float* x    = (const float*)d_in[0];
    const float* Wih  = (const float*)d_in[1];
    const float* Whh  = (const float*)d_in[2];
    const float* bih  = (const float*)d_in[3];
    const float* bhh  = (const float*)d_in[4];
    const float* fc_w = (const float*)d_in[5];
    const float* fc_b = (const float*)d_in[6];
    float* out = (float*)d_out;

    cudaFuncSetAttribute(lstm_persist_tc,
                         cudaFuncAttributeMaxDynamicSharedMemorySize, PSMEM_BYTES);

    conv_x<<<TB_, 256>>>(x);

    const dim3 ggrid(G_ / BN, TB_ / BM);   // (32, 256)
    const int out_sel[L_] = { 0, 1, 0, 1 };

    for (int l = 0; l < L_; l++) {
        conv_w<<<G_, 256>>>(Wih, l);
        void* a_ptr = nullptr;
        if (l == 0) {
            cudaGetSymbolAddress(&a_ptr, g_xh);
        } else if (out_sel[l - 1] == 0) {
            cudaGetSymbolAddress(&a_ptr, g_seqh0);
        } else {
            cudaGetSymbolAddress(&a_ptr, g_seqh1);
        }
        gemm_gates_h<<<ggrid, 256>>>((const __half*)a_ptr, bih, bhh, l);
        lstm_persist_tc<<<NBLK, NTHR, PSMEM_BYTES>>>(Whh, l, out_sel[l]);
    }
    fc_kernel<<<B_, 256>>>(fc_w, fc_b, out);
}